// round 1
// baseline (speedup 1.0000x reference)
#include <cuda_runtime.h>

// ---------------------------------------------------------------------------
// Problem constants
//   x:  (512, 6, 66, 256) fp32
//   Wq/Wk/Wv: (256, 256), bq/bk/bv: (256,)
//   Wc: (22, 66), bc: (22,)
//   out: (512, 132, 256) fp32
// ---------------------------------------------------------------------------
#define BATCH 512
#define TLEN  6
#define SEQ   66
#define INDIM 256
#define HEADS 8
#define HDIM  32
#define JN    22
#define NEGV  (-9e15f)

#define M_TOTAL (BATCH * TLEN * SEQ)          // 202752
#define BTH     (BATCH * TLEN * HEADS)        // 24576
#define TILE_ELEMS (SEQ * HDIM)               // 2112

// Scratch: per-(b,t,h) contiguous [S][D] tiles.
__device__ float g_q[BTH * TILE_ELEMS];
__device__ float g_k[BTH * TILE_ELEMS];
__device__ float g_v[BTH * TILE_ELEMS];

// ---------------------------------------------------------------------------
// Kernel 1: QKV projection GEMM.
//   C(202752 x 768) = x(202752 x 256) @ W^T, W = [Wq; Wk; Wv] (rows = out chan)
//   Tiles: BM=64, BN=64, BK=32.  256 threads, 4x4 microtile per thread.
//   N tiles never straddle a weight matrix (256 % 64 == 0).
// ---------------------------------------------------------------------------
__global__ __launch_bounds__(256) void qkv_gemm(
    const float* __restrict__ x,
    const float* __restrict__ Wq, const float* __restrict__ bq,
    const float* __restrict__ Wk, const float* __restrict__ bk,
    const float* __restrict__ Wv, const float* __restrict__ bv)
{
    __shared__ float As[32][68];   // [k][m], padded
    __shared__ float Bs[32][68];   // [k][n], padded

    const int nb  = blockIdx.x;          // 0..11
    const int mb  = blockIdx.y;          // 0..3167
    const int n0  = nb * 64;
    const int mat = n0 >> 8;             // 0=q 1=k 2=v
    const int nl0 = n0 & 255;            // column base inside the matrix

    const float* W    = (mat == 0) ? Wq : (mat == 1) ? Wk : Wv;
    const float* bias = (mat == 0) ? bq : (mat == 1) ? bk : bv;
    float*       dst  = (mat == 0) ? g_q : (mat == 1) ? g_k : g_v;

    const int tid = threadIdx.x;
    const int m0  = mb * 64;

    const int lrow = tid >> 3;           // 0..31
    const int lk   = (tid & 7) << 2;     // 0,4,...,28

    const int ty = tid >> 4;             // 0..15
    const int tx = tid & 15;             // 0..15

    float acc[4][4];
    #pragma unroll
    for (int i = 0; i < 4; i++)
        #pragma unroll
        for (int j = 0; j < 4; j++) acc[i][j] = 0.0f;

    for (int kb = 0; kb < INDIM; kb += 32) {
        #pragma unroll
        for (int r = 0; r < 2; r++) {
            const int row = lrow + r * 32;
            const float4 a = *(const float4*)&x[(m0 + row) * INDIM + kb + lk];
            As[lk + 0][row] = a.x; As[lk + 1][row] = a.y;
            As[lk + 2][row] = a.z; As[lk + 3][row] = a.w;
            const float4 b = *(const float4*)&W[(nl0 + row) * INDIM + kb + lk];
            Bs[lk + 0][row] = b.x; Bs[lk + 1][row] = b.y;
            Bs[lk + 2][row] = b.z; Bs[lk + 3][row] = b.w;
        }
        __syncthreads();

        #pragma unroll
        for (int kk = 0; kk < 32; kk++) {
            const float4 av = *(const float4*)&As[kk][ty * 4];
            const float4 bv4 = *(const float4*)&Bs[kk][tx * 4];
            const float a_[4] = {av.x, av.y, av.z, av.w};
            const float b_[4] = {bv4.x, bv4.y, bv4.z, bv4.w};
            #pragma unroll
            for (int i = 0; i < 4; i++)
                #pragma unroll
                for (int j = 0; j < 4; j++)
                    acc[i][j] += a_[i] * b_[j];
        }
        __syncthreads();
    }

    // Epilogue: bias (+relu for V), scatter to per-(bt,h) [S][D] tiles.
    const int cbase = nl0 + tx * 4;      // local out channel (mult of 4)
    const int h = cbase >> 5;
    const int d = cbase & 31;            // d..d+3 stays inside one head
    float bi[4];
    #pragma unroll
    for (int j = 0; j < 4; j++) bi[j] = bias[cbase + j];

    #pragma unroll
    for (int i = 0; i < 4; i++) {
        const int m  = m0 + ty * 4 + i;
        const int bt = m / SEQ;
        const int s  = m - bt * SEQ;
        float4 o;
        o.x = acc[i][0] + bi[0];
        o.y = acc[i][1] + bi[1];
        o.z = acc[i][2] + bi[2];
        o.w = acc[i][3] + bi[3];
        if (mat == 2) {
            o.x = fmaxf(o.x, 0.0f); o.y = fmaxf(o.y, 0.0f);
            o.z = fmaxf(o.z, 0.0f); o.w = fmaxf(o.w, 0.0f);
        }
        *(float4*)&dst[((bt * HEADS + h) * SEQ + s) * HDIM + d] = o;
    }
}

// ---------------------------------------------------------------------------
// Kernel 2: per-(b,t,h) attention + classifier.  One block each, 256 threads.
//   smem: q^T[32][72], k^T[32][72], v[66][32], scores[68][72]
//   ao (attn@v, [68][32]) overlays q^T (dead after score phase).
// ---------------------------------------------------------------------------
__global__ __launch_bounds__(256) void attn_kernel(
    const float* __restrict__ Wc, const float* __restrict__ bc,
    float* __restrict__ out)
{
    __shared__ float qst[32][72];
    __shared__ float kst[32][72];
    __shared__ float vs[SEQ][32];
    __shared__ float sc[68][72];
    float* ao = &qst[0][0];              // [68][32] overlay (2176 <= 2304 floats)

    const int bid = blockIdx.x;          // 0..24575  == (bt*8 + h)
    const int tid = threadIdx.x;

    const float* qg = g_q + (size_t)bid * TILE_ELEMS;
    const float* kg = g_k + (size_t)bid * TILE_ELEMS;
    const float* vg = g_v + (size_t)bid * TILE_ELEMS;

    // ---- stage tiles (transpose q,k into [d][s]) ----
    for (int idx = tid; idx < SEQ * 8; idx += 256) {   // 528 float4 per tensor
        const int s = idx >> 3;
        const int d = (idx & 7) << 2;
        const float4 q4 = *(const float4*)&qg[s * 32 + d];
        qst[d + 0][s] = q4.x; qst[d + 1][s] = q4.y;
        qst[d + 2][s] = q4.z; qst[d + 3][s] = q4.w;
        const float4 k4 = *(const float4*)&kg[s * 32 + d];
        kst[d + 0][s] = k4.x; kst[d + 1][s] = k4.y;
        kst[d + 2][s] = k4.z; kst[d + 3][s] = k4.w;
        *(float4*)&vs[s][d] = *(const float4*)&vg[s * 32 + d];
    }
    if (tid < 32) {
        #pragma unroll
        for (int c = SEQ; c < 72; c++) { qst[tid][c] = 0.0f; kst[tid][c] = 0.0f; }
    }
    __syncthreads();

    // ---- scores: 17x17 tiles of 4x4 over padded 68x68 ----
    const float scale = 0.17677669529663687f;   // 1/sqrt(32)
    for (int tt = tid; tt < 289; tt += 256) {
        const int sq0 = (tt / 17) << 2;
        const int sk0 = (tt % 17) << 2;
        float a[4][4];
        #pragma unroll
        for (int i = 0; i < 4; i++)
            #pragma unroll
            for (int j = 0; j < 4; j++) a[i][j] = 0.0f;
        #pragma unroll
        for (int kk = 0; kk < 32; kk++) {
            const float4 qv = *(const float4*)&qst[kk][sq0];
            const float4 kv = *(const float4*)&kst[kk][sk0];
            const float qa[4] = {qv.x, qv.y, qv.z, qv.w};
            const float ka[4] = {kv.x, kv.y, kv.z, kv.w};
            #pragma unroll
            for (int i = 0; i < 4; i++)
                #pragma unroll
                for (int j = 0; j < 4; j++)
                    a[i][j] += qa[i] * ka[j];
        }
        #pragma unroll
        for (int i = 0; i < 4; i++) {
            const int sq = sq0 + i;
            #pragma unroll
            for (int j = 0; j < 4; j++) {
                const int sk = sk0 + j;
                float v = a[i][j] * scale;
                const bool mz = (sq < JN && sk >= 2 * JN) ||
                                (sq >= 2 * JN && sk < JN);
                sc[sq][sk] = mz ? 0.0f : v;
            }
        }
    }
    __syncthreads();

    // ---- rowmax -> threshold prune -> softmax (one warp per row) ----
    {
        const int warp = tid >> 5, lane = tid & 31;
        const float NINF = __int_as_float(0xff800000);
        for (int r = warp; r < SEQ; r += 8) {
            float e0 = sc[r][lane];
            float e1 = sc[r][lane + 32];
            float e2 = (lane < 2) ? sc[r][lane + 64] : NINF;
            float mx = fmaxf(fmaxf(e0, e1), e2);
            #pragma unroll
            for (int off = 16; off > 0; off >>= 1)
                mx = fmaxf(mx, __shfl_xor_sync(0xffffffffu, mx, off));
            const float thr = mx / 9.0f;
            e0 = (fabsf(e0) <= thr) ? NEGV : e0;
            e1 = (fabsf(e1) <= thr) ? NEGV : e1;
            e2 = (fabsf(e2) <= thr) ? NEGV : e2;   // NINF lanes stay NINF
            float mx2 = fmaxf(fmaxf(e0, e1), e2);
            #pragma unroll
            for (int off = 16; off > 0; off >>= 1)
                mx2 = fmaxf(mx2, __shfl_xor_sync(0xffffffffu, mx2, off));
            const float ex0 = __expf(e0 - mx2);
            const float ex1 = __expf(e1 - mx2);
            const float ex2 = (lane < 2) ? __expf(e2 - mx2) : 0.0f;
            float sum = ex0 + ex1 + ex2;
            #pragma unroll
            for (int off = 16; off > 0; off >>= 1)
                sum += __shfl_xor_sync(0xffffffffu, sum, off);
            const float inv = 1.0f / sum;
            sc[r][lane]      = ex0 * inv;
            sc[r][lane + 32] = ex1 * inv;
            if (lane < 2) sc[r][lane + 64] = ex2 * inv;
        }
    }
    __syncthreads();

    // ---- AV: ao[sq][d] = sum_sk p[sq][sk] * v[sk][d] ----
    if (tid < 136) {                      // 17 x 8 tiles of 4sq x 4d
        const int sq0 = (tid >> 3) << 2;
        const int d0  = (tid & 7) << 2;
        float4 acc[4];
        #pragma unroll
        for (int i = 0; i < 4; i++) acc[i] = make_float4(0.f, 0.f, 0.f, 0.f);
        for (int sk = 0; sk < SEQ; sk++) {
            const float4 vv = *(const float4*)&vs[sk][d0];
            #pragma unroll
            for (int i = 0; i < 4; i++) {
                const float p = sc[sq0 + i][sk];
                acc[i].x += p * vv.x; acc[i].y += p * vv.y;
                acc[i].z += p * vv.z; acc[i].w += p * vv.w;
            }
        }
        #pragma unroll
        for (int i = 0; i < 4; i++)
            *(float4*)&ao[(sq0 + i) * 32 + d0] = acc[i];
    }
    __syncthreads();

    // ---- classifier: out2[j][d] = sum_s ao[s][d]*Wc[j][s] + bc[j] ----
    if (tid < JN * 8) {                   // 176 tasks: (j, 4-wide d)
        const int j  = tid >> 3;
        const int d0 = (tid & 7) << 2;
        float4 acc = make_float4(0.f, 0.f, 0.f, 0.f);
        for (int s = 0; s < SEQ; s++) {
            const float w = __ldg(&Wc[j * SEQ + s]);
            const float4 av = *(const float4*)&ao[s * 32 + d0];
            acc.x += w * av.x; acc.y += w * av.y;
            acc.z += w * av.z; acc.w += w * av.w;
        }
        const float bcv = __ldg(&bc[j]);
        acc.x += bcv; acc.y += bcv; acc.z += bcv; acc.w += bcv;

        const int h  = bid & 7;
        const int bt = bid >> 3;
        const int b  = bt / TLEN;
        const int t  = bt - b * TLEN;
        const size_t off = ((size_t)b * (TLEN * JN) + t * JN + j) * (HEADS * HDIM)
                         + h * HDIM + d0;
        *(float4*)&out[off] = acc;
    }
}

// ---------------------------------------------------------------------------
extern "C" void kernel_launch(void* const* d_in, const int* in_sizes, int n_in,
                              void* d_out, int out_size)
{
    const float* x  = (const float*)d_in[0];
    const float* Wq = (const float*)d_in[1];
    const float* bq = (const float*)d_in[2];
    const float* Wk = (const float*)d_in[3];
    const float* bk = (const float*)d_in[4];
    const float* Wv = (const float*)d_in[5];
    const float* bv = (const float*)d_in[6];
    const float* Wc = (const float*)d_in[7];
    const float* bc = (const float*)d_in[8];
    float* out = (float*)d_out;

    dim3 g1(768 / 64, M_TOTAL / 64);     // (12, 3168)
    qkv_gemm<<<g1, 256>>>(x, Wq, bq, Wk, bk, Wv, bv);
    attn_kernel<<<BTH, 256>>>(Wc, bc, out);
}

// round 4
// speedup vs baseline: 1.7319x; 1.7319x over previous
#include <cuda_runtime.h>
#include <cuda_fp16.h>
#include <cstdint>

// ---------------------------------------------------------------------------
// Problem constants
// ---------------------------------------------------------------------------
#define BATCH 512
#define TLEN  6
#define SEQ   66
#define INDIM 256
#define HEADS 8
#define HDIM  32
#define JN    22
#define NEGV  (-9e15f)

#define M_TOTAL (BATCH * TLEN * SEQ)          // 202752  (= 1584 * 128)
#define BTH     (BATCH * TLEN * HEADS)        // 24576
#define TILE_ELEMS (SEQ * HDIM)               // 2112

// Scratch
__device__ float g_q[BTH * TILE_ELEMS];
__device__ float g_k[BTH * TILE_ELEMS];
__device__ float g_v[BTH * TILE_ELEMS];
__device__ __half g_wh[3 * 256 * 256];        // weights fp16 hi
__device__ __half g_wl[3 * 256 * 256];        // weights fp16 lo

// ---------------------------------------------------------------------------
// m16n8k16 HMMA, f32 accum  (base sm_103-legal; no tcgen05)
// ---------------------------------------------------------------------------
__device__ __forceinline__ void hmma(float* c, const uint32_t* a, const uint32_t* b) {
    asm volatile(
        "mma.sync.aligned.m16n8k16.row.col.f32.f16.f16.f32 "
        "{%0,%1,%2,%3}, {%4,%5,%6,%7}, {%8,%9}, {%0,%1,%2,%3};"
        : "+f"(c[0]), "+f"(c[1]), "+f"(c[2]), "+f"(c[3])
        : "r"(a[0]), "r"(a[1]), "r"(a[2]), "r"(a[3]), "r"(b[0]), "r"(b[1]));
}

__device__ __forceinline__ uint32_t pack2(__half a, __half b) {
    __half2 h = __halves2half2(a, b);
    return *(uint32_t*)&h;
}

// ---------------------------------------------------------------------------
// Kernel 0: split W (Wq|Wk|Wv) to fp16 hi/lo.
// ---------------------------------------------------------------------------
__global__ void wconv(const float* __restrict__ Wq, const float* __restrict__ Wk,
                      const float* __restrict__ Wv) {
    const int i = blockIdx.x * 256 + threadIdx.x;       // < 196608
    const int mat = i >> 16;
    const int rem = i & 65535;
    const float* W = (mat == 0) ? Wq : (mat == 1) ? Wk : Wv;
    const float v = W[rem];
    const __half h = __float2half(v);
    g_wh[i] = h;
    g_wl[i] = __float2half(v - __half2float(h));
}

// ---------------------------------------------------------------------------
// Kernel 1: QKV GEMM, split-fp16 3-MMA on HMMA.
//   grid = (2, 1584, 3): x = N-tile (128 of 256), y = M-tile(128), z = matrix.
//   Block 128x128x(K=256 in BK=32 chunks). 8 warps, warp tile 64x32.
//   smem: A(hi,lo) 128x32 + B(hi,lo) 128x32, pad-40 halves => 40960 B.
// ---------------------------------------------------------------------------
#define APAD 40

__global__ __launch_bounds__(256) void qkv_gemm_tc(
    const float* __restrict__ x,
    const float* __restrict__ bq, const float* __restrict__ bk,
    const float* __restrict__ bv)
{
    __shared__ __half Ash[128 * APAD];
    __shared__ __half Asl[128 * APAD];
    __shared__ __half Bsh[128 * APAD];
    __shared__ __half Bsl[128 * APAD];

    const int tid  = threadIdx.x;
    const int wid  = tid >> 5, lane = tid & 31;
    const int mat  = blockIdx.z;                  // 0=q 1=k 2=v
    const int m0   = blockIdx.y * 128;
    const int n0g  = blockIdx.x * 128;            // global col base in the matrix

    const float*  xg = x + (size_t)m0 * INDIM;
    const __half* wh = g_wh + mat * 65536 + (size_t)n0g * 256;
    const __half* wl = g_wl + mat * 65536 + (size_t)n0g * 256;

    // warp tiling: 2 (m) x 4 (n)
    const int warpM = (wid & 1) * 64;
    const int warpN = (wid >> 1) * 32;

    float acc[4][4][4];
    #pragma unroll
    for (int i = 0; i < 4; i++)
        #pragma unroll
        for (int j = 0; j < 4; j++)
            #pragma unroll
            for (int e = 0; e < 4; e++) acc[i][j][e] = 0.0f;

    // prefetch registers
    float4 pa[4];          // 4 float4 of x   (rows: tid>>3 + i*... see below)
    uint4  pbh[2], pbl[2]; // B chunks

    // addressing for A loads: 1024 float4 per chunk -> 4 per thread
    //   idx = tid + i*256 ; row = idx>>3 ; c4 = (idx&7)*4
    // addressing for B loads: 512 uint4 per split -> 2 per thread per split
    //   idx = tid + i*256 ; row = idx>>2 ; q = idx&3 (16B units)

    auto loadA = [&](int kc) {
        #pragma unroll
        for (int i = 0; i < 4; i++) {
            const int idx = tid + i * 256;
            const int row = idx >> 3, c4 = (idx & 7) << 2;
            pa[i] = *(const float4*)(xg + (size_t)row * INDIM + kc + c4);
        }
    };
    auto loadB = [&](int kc) {
        #pragma unroll
        for (int i = 0; i < 2; i++) {
            const int idx = tid + i * 256;
            const int row = idx >> 2, q = idx & 3;
            pbh[i] = *(const uint4*)(wh + (size_t)row * 256 + kc + q * 8);
            pbl[i] = *(const uint4*)(wl + (size_t)row * 256 + kc + q * 8);
        }
    };
    auto storeA = [&]() {
        #pragma unroll
        for (int i = 0; i < 4; i++) {
            const int idx = tid + i * 256;
            const int row = idx >> 3, c4 = (idx & 7) << 2;
            const float v0 = pa[i].x, v1 = pa[i].y, v2 = pa[i].z, v3 = pa[i].w;
            const __half h0 = __float2half(v0), h1 = __float2half(v1);
            const __half h2 = __float2half(v2), h3 = __float2half(v3);
            const __half l0 = __float2half(v0 - __half2float(h0));
            const __half l1 = __float2half(v1 - __half2float(h1));
            const __half l2 = __float2half(v2 - __half2float(h2));
            const __half l3 = __float2half(v3 - __half2float(h3));
            uint2 ph = make_uint2(pack2(h0, h1), pack2(h2, h3));
            uint2 pl = make_uint2(pack2(l0, l1), pack2(l2, l3));
            *(uint2*)(Ash + row * APAD + c4) = ph;
            *(uint2*)(Asl + row * APAD + c4) = pl;
        }
    };
    auto storeB = [&]() {
        #pragma unroll
        for (int i = 0; i < 2; i++) {
            const int idx = tid + i * 256;
            const int row = idx >> 2, q = idx & 3;
            *(uint4*)(Bsh + row * APAD + q * 8) = pbh[i];
            *(uint4*)(Bsl + row * APAD + q * 8) = pbl[i];
        }
    };

    loadA(0); loadB(0);
    storeA(); storeB();
    __syncthreads();

    for (int c = 0; c < 8; c++) {
        if (c < 7) { loadA((c + 1) * 32); loadB((c + 1) * 32); }

        #pragma unroll
        for (int ks = 0; ks < 2; ks++) {
            const int k0 = ks * 16;
            uint32_t ah[4][4], al[4][4], bh[4][2], bl[4][2];
            #pragma unroll
            for (int mf = 0; mf < 4; mf++) {
                const int r = warpM + mf * 16 + (lane >> 2);
                const int cc = k0 + ((lane & 3) << 1);
                ah[mf][0] = *(const uint32_t*)(Ash + r * APAD + cc);
                ah[mf][1] = *(const uint32_t*)(Ash + (r + 8) * APAD + cc);
                ah[mf][2] = *(const uint32_t*)(Ash + r * APAD + cc + 8);
                ah[mf][3] = *(const uint32_t*)(Ash + (r + 8) * APAD + cc + 8);
                al[mf][0] = *(const uint32_t*)(Asl + r * APAD + cc);
                al[mf][1] = *(const uint32_t*)(Asl + (r + 8) * APAD + cc);
                al[mf][2] = *(const uint32_t*)(Asl + r * APAD + cc + 8);
                al[mf][3] = *(const uint32_t*)(Asl + (r + 8) * APAD + cc + 8);
            }
            #pragma unroll
            for (int nf = 0; nf < 4; nf++) {
                const int n = warpN + nf * 8 + (lane >> 2);
                const int kk = k0 + ((lane & 3) << 1);
                bh[nf][0] = *(const uint32_t*)(Bsh + n * APAD + kk);
                bh[nf][1] = *(const uint32_t*)(Bsh + n * APAD + kk + 8);
                bl[nf][0] = *(const uint32_t*)(Bsl + n * APAD + kk);
                bl[nf][1] = *(const uint32_t*)(Bsl + n * APAD + kk + 8);
            }
            #pragma unroll
            for (int mf = 0; mf < 4; mf++)
                #pragma unroll
                for (int nf = 0; nf < 4; nf++) {
                    hmma(acc[mf][nf], ah[mf], bh[nf]);
                    hmma(acc[mf][nf], ah[mf], bl[nf]);
                    hmma(acc[mf][nf], al[mf], bh[nf]);
                }
        }
        __syncthreads();
        if (c < 7) {
            storeA(); storeB();
            __syncthreads();
        }
    }

    // ---- epilogue: bias (+relu for V), scatter to per-(bt,h) [S][D] tiles ----
    const float* bias = (mat == 0) ? bq : (mat == 1) ? bk : bv;
    float* dst        = (mat == 0) ? g_q : (mat == 1) ? g_k : g_v;

    #pragma unroll
    for (int nf = 0; nf < 4; nf++) {
        const int col = n0g + warpN + nf * 8 + ((lane & 3) << 1);
        const int h = col >> 5, d = col & 31;
        const float b0 = bias[col], b1 = bias[col + 1];
        #pragma unroll
        for (int mf = 0; mf < 4; mf++) {
            #pragma unroll
            for (int half = 0; half < 2; half++) {
                const int m = m0 + warpM + mf * 16 + (lane >> 2) + half * 8;
                const int bt = m / SEQ;
                const int s  = m - bt * SEQ;
                float o0 = acc[mf][nf][half * 2 + 0] + b0;
                float o1 = acc[mf][nf][half * 2 + 1] + b1;
                if (mat == 2) { o0 = fmaxf(o0, 0.f); o1 = fmaxf(o1, 0.f); }
                float2 o = make_float2(o0, o1);
                *(float2*)(dst + (((size_t)(bt * HEADS + h)) * SEQ + s) * HDIM + d) = o;
            }
        }
    }
}

// ---------------------------------------------------------------------------
// Kernel 2: per-(b,t,h) attention + classifier (unchanged passing version).
// ---------------------------------------------------------------------------
__global__ __launch_bounds__(256) void attn_kernel(
    const float* __restrict__ Wc, const float* __restrict__ bc,
    float* __restrict__ out)
{
    __shared__ float qst[32][72];
    __shared__ float kst[32][72];
    __shared__ float vs[SEQ][32];
    __shared__ float sc[68][72];
    float* ao = &qst[0][0];

    const int bid = blockIdx.x;
    const int tid = threadIdx.x;

    const float* qg = g_q + (size_t)bid * TILE_ELEMS;
    const float* kg = g_k + (size_t)bid * TILE_ELEMS;
    const float* vg = g_v + (size_t)bid * TILE_ELEMS;

    for (int idx = tid; idx < SEQ * 8; idx += 256) {
        const int s = idx >> 3;
        const int d = (idx & 7) << 2;
        const float4 q4 = *(const float4*)&qg[s * 32 + d];
        qst[d + 0][s] = q4.x; qst[d + 1][s] = q4.y;
        qst[d + 2][s] = q4.z; qst[d + 3][s] = q4.w;
        const float4 k4 = *(const float4*)&kg[s * 32 + d];
        kst[d + 0][s] = k4.x; kst[d + 1][s] = k4.y;
        kst[d + 2][s] = k4.z; kst[d + 3][s] = k4.w;
        *(float4*)&vs[s][d] = *(const float4*)&vg[s * 32 + d];
    }
    if (tid < 32) {
        #pragma unroll
        for (int c = SEQ; c < 72; c++) { qst[tid][c] = 0.0f; kst[tid][c] = 0.0f; }
    }
    __syncthreads();

    const float scale = 0.17677669529663687f;
    for (int tt = tid; tt < 289; tt += 256) {
        const int sq0 = (tt / 17) << 2;
        const int sk0 = (tt % 17) << 2;
        float a[4][4];
        #pragma unroll
        for (int i = 0; i < 4; i++)
            #pragma unroll
            for (int j = 0; j < 4; j++) a[i][j] = 0.0f;
        #pragma unroll
        for (int kk = 0; kk < 32; kk++) {
            const float4 qv = *(const float4*)&qst[kk][sq0];
            const float4 kv = *(const float4*)&kst[kk][sk0];
            const float qa[4] = {qv.x, qv.y, qv.z, qv.w};
            const float ka[4] = {kv.x, kv.y, kv.z, kv.w};
            #pragma unroll
            for (int i = 0; i < 4; i++)
                #pragma unroll
                for (int j = 0; j < 4; j++)
                    a[i][j] += qa[i] * ka[j];
        }
        #pragma unroll
        for (int i = 0; i < 4; i++) {
            const int sq = sq0 + i;
            #pragma unroll
            for (int j = 0; j < 4; j++) {
                const int sk = sk0 + j;
                float v = a[i][j] * scale;
                const bool mz = (sq < JN && sk >= 2 * JN) ||
                                (sq >= 2 * JN && sk < JN);
                sc[sq][sk] = mz ? 0.0f : v;
            }
        }
    }
    __syncthreads();

    {
        const int warp = tid >> 5, lane = tid & 31;
        const float NINF = __int_as_float(0xff800000);
        for (int r = warp; r < SEQ; r += 8) {
            float e0 = sc[r][lane];
            float e1 = sc[r][lane + 32];
            float e2 = (lane < 2) ? sc[r][lane + 64] : NINF;
            float mx = fmaxf(fmaxf(e0, e1), e2);
            #pragma unroll
            for (int off = 16; off > 0; off >>= 1)
                mx = fmaxf(mx, __shfl_xor_sync(0xffffffffu, mx, off));
            const float thr = mx / 9.0f;
            e0 = (fabsf(e0) <= thr) ? NEGV : e0;
            e1 = (fabsf(e1) <= thr) ? NEGV : e1;
            e2 = (fabsf(e2) <= thr) ? NEGV : e2;
            float mx2 = fmaxf(fmaxf(e0, e1), e2);
            #pragma unroll
            for (int off = 16; off > 0; off >>= 1)
                mx2 = fmaxf(mx2, __shfl_xor_sync(0xffffffffu, mx2, off));
            const float ex0 = __expf(e0 - mx2);
            const float ex1 = __expf(e1 - mx2);
            const float ex2 = (lane < 2) ? __expf(e2 - mx2) : 0.0f;
            float sum = ex0 + ex1 + ex2;
            #pragma unroll
            for (int off = 16; off > 0; off >>= 1)
                sum += __shfl_xor_sync(0xffffffffu, sum, off);
            const float inv = 1.0f / sum;
            sc[r][lane]      = ex0 * inv;
            sc[r][lane + 32] = ex1 * inv;
            if (lane < 2) sc[r][lane + 64] = ex2 * inv;
        }
    }
    __syncthreads();

    if (tid < 136) {
        const int sq0 = (tid >> 3) << 2;
        const int d0  = (tid & 7) << 2;
        float4 acc[4];
        #pragma unroll
        for (int i = 0; i < 4; i++) acc[i] = make_float4(0.f, 0.f, 0.f, 0.f);
        for (int sk = 0; sk < SEQ; sk++) {
            const float4 vv = *(const float4*)&vs[sk][d0];
            #pragma unroll
            for (int i = 0; i < 4; i++) {
                const float p = sc[sq0 + i][sk];
                acc[i].x += p * vv.x; acc[i].y += p * vv.y;
                acc[i].z += p * vv.z; acc[i].w += p * vv.w;
            }
        }
        #pragma unroll
        for (int i = 0; i < 4; i++)
            *(float4*)&ao[(sq0 + i) * 32 + d0] = acc[i];
    }
    __syncthreads();

    if (tid < JN * 8) {
        const int j  = tid >> 3;
        const int d0 = (tid & 7) << 2;
        float4 acc = make_float4(0.f, 0.f, 0.f, 0.f);
        for (int s = 0; s < SEQ; s++) {
            const float w = __ldg(&Wc[j * SEQ + s]);
            const float4 av = *(const float4*)&ao[s * 32 + d0];
            acc.x += w * av.x; acc.y += w * av.y;
            acc.z += w * av.z; acc.w += w * av.w;
        }
        const float bcv = __ldg(&bc[j]);
        acc.x += bcv; acc.y += bcv; acc.z += bcv; acc.w += bcv;

        const int h  = bid & 7;
        const int bt = bid >> 3;
        const int b  = bt / TLEN;
        const int t  = bt - b * TLEN;
        const size_t off = ((size_t)b * (TLEN * JN) + t * JN + j) * (HEADS * HDIM)
                         + h * HDIM + d0;
        *(float4*)&out[off] = acc;
    }
}

// ---------------------------------------------------------------------------
extern "C" void kernel_launch(void* const* d_in, const int* in_sizes, int n_in,
                              void* d_out, int out_size)
{
    const float* x  = (const float*)d_in[0];
    const float* Wq = (const float*)d_in[1];
    const float* bq = (const float*)d_in[2];
    const float* Wk = (const float*)d_in[3];
    const float* bk = (const float*)d_in[4];
    const float* Wv = (const float*)d_in[5];
    const float* bv = (const float*)d_in[6];
    const float* Wc = (const float*)d_in[7];
    const float* bc = (const float*)d_in[8];
    float* out = (float*)d_out;

    wconv<<<768, 256>>>(Wq, Wk, Wv);
    qkv_gemm_tc<<<dim3(2, M_TOTAL / 128, 3), 256>>>(x, bq, bk, bv);
    attn_kernel<<<BTH, 256>>>(Wc, bc, out);
}

// round 5
// speedup vs baseline: 1.7683x; 1.0210x over previous
#include <cuda_runtime.h>
#include <cuda_fp16.h>
#include <cstdint>

// ---------------------------------------------------------------------------
// Problem constants
// ---------------------------------------------------------------------------
#define BATCH 512
#define TLEN  6
#define SEQ   66
#define INDIM 256
#define HEADS 8
#define HDIM  32
#define JN    22
#define NEGV  (-9e15f)

#define M_TOTAL (BATCH * TLEN * SEQ)          // 202752  (= 1584 * 128)
#define BTH     (BATCH * TLEN * HEADS)        // 24576
#define TILE_ELEMS (SEQ * HDIM)               // 2112

// Scratch: q/k/v as packed fp16 hi|lo (hi = bits[0:16], lo = bits[16:32]).
__device__ uint32_t g_q[BTH * TILE_ELEMS];
__device__ uint32_t g_k[BTH * TILE_ELEMS];
__device__ uint32_t g_v[BTH * TILE_ELEMS];
__device__ __half g_wh[3 * 256 * 256];        // weights fp16 hi
__device__ __half g_wl[3 * 256 * 256];        // weights fp16 lo

// ---------------------------------------------------------------------------
// m16n8k16 HMMA, f32 accum (base sm_103-legal)
// ---------------------------------------------------------------------------
__device__ __forceinline__ void hmma(float* c, const uint32_t* a, const uint32_t* b) {
    asm volatile(
        "mma.sync.aligned.m16n8k16.row.col.f32.f16.f16.f32 "
        "{%0,%1,%2,%3}, {%4,%5,%6,%7}, {%8,%9}, {%0,%1,%2,%3};"
        : "+f"(c[0]), "+f"(c[1]), "+f"(c[2]), "+f"(c[3])
        : "r"(a[0]), "r"(a[1]), "r"(a[2]), "r"(a[3]), "r"(b[0]), "r"(b[1]));
}

__device__ __forceinline__ uint32_t pack2(__half a, __half b) {
    __half2 h = __halves2half2(a, b);
    return *(uint32_t*)&h;
}
__device__ __forceinline__ uint32_t pack_hilo(float v) {
    const __half h = __float2half(v);
    const __half l = __float2half(v - __half2float(h));
    return (uint32_t)__half_as_ushort(h) | ((uint32_t)__half_as_ushort(l) << 16);
}

// ---------------------------------------------------------------------------
// Kernel 0: split W (Wq|Wk|Wv) to fp16 hi/lo.
// ---------------------------------------------------------------------------
__global__ void wconv(const float* __restrict__ Wq, const float* __restrict__ Wk,
                      const float* __restrict__ Wv) {
    const int i = blockIdx.x * 256 + threadIdx.x;       // < 196608
    const int mat = i >> 16;
    const int rem = i & 65535;
    const float* W = (mat == 0) ? Wq : (mat == 1) ? Wk : Wv;
    const float v = W[rem];
    const __half h = __float2half(v);
    g_wh[i] = h;
    g_wl[i] = __float2half(v - __half2float(h));
}

// ---------------------------------------------------------------------------
// Kernel 1: QKV GEMM, split-fp16 3-MMA on HMMA (passing R4 version; epilogue
// now writes packed hi|lo u32).
// ---------------------------------------------------------------------------
#define APAD 40

__global__ __launch_bounds__(256) void qkv_gemm_tc(
    const float* __restrict__ x,
    const float* __restrict__ bq, const float* __restrict__ bk,
    const float* __restrict__ bv)
{
    __shared__ __half Ash[128 * APAD];
    __shared__ __half Asl[128 * APAD];
    __shared__ __half Bsh[128 * APAD];
    __shared__ __half Bsl[128 * APAD];

    const int tid  = threadIdx.x;
    const int wid  = tid >> 5, lane = tid & 31;
    const int mat  = blockIdx.z;
    const int m0   = blockIdx.y * 128;
    const int n0g  = blockIdx.x * 128;

    const float*  xg = x + (size_t)m0 * INDIM;
    const __half* wh = g_wh + mat * 65536 + (size_t)n0g * 256;
    const __half* wl = g_wl + mat * 65536 + (size_t)n0g * 256;

    const int warpM = (wid & 1) * 64;
    const int warpN = (wid >> 1) * 32;

    float acc[4][4][4];
    #pragma unroll
    for (int i = 0; i < 4; i++)
        #pragma unroll
        for (int j = 0; j < 4; j++)
            #pragma unroll
            for (int e = 0; e < 4; e++) acc[i][j][e] = 0.0f;

    float4 pa[4];
    uint4  pbh[2], pbl[2];

    auto loadA = [&](int kc) {
        #pragma unroll
        for (int i = 0; i < 4; i++) {
            const int idx = tid + i * 256;
            const int row = idx >> 3, c4 = (idx & 7) << 2;
            pa[i] = *(const float4*)(xg + (size_t)row * INDIM + kc + c4);
        }
    };
    auto loadB = [&](int kc) {
        #pragma unroll
        for (int i = 0; i < 2; i++) {
            const int idx = tid + i * 256;
            const int row = idx >> 2, q = idx & 3;
            pbh[i] = *(const uint4*)(wh + (size_t)row * 256 + kc + q * 8);
            pbl[i] = *(const uint4*)(wl + (size_t)row * 256 + kc + q * 8);
        }
    };
    auto storeA = [&]() {
        #pragma unroll
        for (int i = 0; i < 4; i++) {
            const int idx = tid + i * 256;
            const int row = idx >> 3, c4 = (idx & 7) << 2;
            const float v0 = pa[i].x, v1 = pa[i].y, v2 = pa[i].z, v3 = pa[i].w;
            const __half h0 = __float2half(v0), h1 = __float2half(v1);
            const __half h2 = __float2half(v2), h3 = __float2half(v3);
            const __half l0 = __float2half(v0 - __half2float(h0));
            const __half l1 = __float2half(v1 - __half2float(h1));
            const __half l2 = __float2half(v2 - __half2float(h2));
            const __half l3 = __float2half(v3 - __half2float(h3));
            uint2 ph = make_uint2(pack2(h0, h1), pack2(h2, h3));
            uint2 pl = make_uint2(pack2(l0, l1), pack2(l2, l3));
            *(uint2*)(Ash + row * APAD + c4) = ph;
            *(uint2*)(Asl + row * APAD + c4) = pl;
        }
    };
    auto storeB = [&]() {
        #pragma unroll
        for (int i = 0; i < 2; i++) {
            const int idx = tid + i * 256;
            const int row = idx >> 2, q = idx & 3;
            *(uint4*)(Bsh + row * APAD + q * 8) = pbh[i];
            *(uint4*)(Bsl + row * APAD + q * 8) = pbl[i];
        }
    };

    loadA(0); loadB(0);
    storeA(); storeB();
    __syncthreads();

    for (int c = 0; c < 8; c++) {
        if (c < 7) { loadA((c + 1) * 32); loadB((c + 1) * 32); }

        #pragma unroll
        for (int ks = 0; ks < 2; ks++) {
            const int k0 = ks * 16;
            uint32_t ah[4][4], al[4][4], bh[4][2], bl[4][2];
            #pragma unroll
            for (int mf = 0; mf < 4; mf++) {
                const int r = warpM + mf * 16 + (lane >> 2);
                const int cc = k0 + ((lane & 3) << 1);
                ah[mf][0] = *(const uint32_t*)(Ash + r * APAD + cc);
                ah[mf][1] = *(const uint32_t*)(Ash + (r + 8) * APAD + cc);
                ah[mf][2] = *(const uint32_t*)(Ash + r * APAD + cc + 8);
                ah[mf][3] = *(const uint32_t*)(Ash + (r + 8) * APAD + cc + 8);
                al[mf][0] = *(const uint32_t*)(Asl + r * APAD + cc);
                al[mf][1] = *(const uint32_t*)(Asl + (r + 8) * APAD + cc);
                al[mf][2] = *(const uint32_t*)(Asl + r * APAD + cc + 8);
                al[mf][3] = *(const uint32_t*)(Asl + (r + 8) * APAD + cc + 8);
            }
            #pragma unroll
            for (int nf = 0; nf < 4; nf++) {
                const int n = warpN + nf * 8 + (lane >> 2);
                const int kk = k0 + ((lane & 3) << 1);
                bh[nf][0] = *(const uint32_t*)(Bsh + n * APAD + kk);
                bh[nf][1] = *(const uint32_t*)(Bsh + n * APAD + kk + 8);
                bl[nf][0] = *(const uint32_t*)(Bsl + n * APAD + kk);
                bl[nf][1] = *(const uint32_t*)(Bsl + n * APAD + kk + 8);
            }
            #pragma unroll
            for (int mf = 0; mf < 4; mf++)
                #pragma unroll
                for (int nf = 0; nf < 4; nf++) {
                    hmma(acc[mf][nf], ah[mf], bh[nf]);
                    hmma(acc[mf][nf], ah[mf], bl[nf]);
                    hmma(acc[mf][nf], al[mf], bh[nf]);
                }
        }
        __syncthreads();
        if (c < 7) {
            storeA(); storeB();
            __syncthreads();
        }
    }

    const float* bias = (mat == 0) ? bq : (mat == 1) ? bk : bv;
    uint32_t* dst     = (mat == 0) ? g_q : (mat == 1) ? g_k : g_v;

    #pragma unroll
    for (int nf = 0; nf < 4; nf++) {
        const int col = n0g + warpN + nf * 8 + ((lane & 3) << 1);
        const int h = col >> 5, d = col & 31;
        const float b0 = bias[col], b1 = bias[col + 1];
        #pragma unroll
        for (int mf = 0; mf < 4; mf++) {
            #pragma unroll
            for (int hf = 0; hf < 2; hf++) {
                const int m = m0 + warpM + mf * 16 + (lane >> 2) + hf * 8;
                const int bt = m / SEQ;
                const int s  = m - bt * SEQ;
                float o0 = acc[mf][nf][hf * 2 + 0] + b0;
                float o1 = acc[mf][nf][hf * 2 + 1] + b1;
                if (mat == 2) { o0 = fmaxf(o0, 0.f); o1 = fmaxf(o1, 0.f); }
                uint2 o = make_uint2(pack_hilo(o0), pack_hilo(o1));
                *(uint2*)(dst + (((size_t)(bt * HEADS + h)) * SEQ + s) * HDIM + d) = o;
            }
        }
    }
}

// ---------------------------------------------------------------------------
// Kernel 2: attention via HMMA scores + (Wc@P)@v refactor.
//   smem map (bytes):
//     Ah q-hi [80][40]h @0      (6400)   } P2 fp32 [22][72] overlays @0 (6336)
//     Al q-lo [80][40]h @6400   (6400)
//     Bh k-hi [72][40]h @12800  (5760)   } v fp32 [68][36] overlays @12800 (9792)
//     Bl k-lo [72][40]h @18560  (5760)
//     sc fp32 [68][76]  @24320  (20672)  total 44992 B
// ---------------------------------------------------------------------------
#define SC_STRIDE 76
#define P2_STRIDE 72
#define V_STRIDE  36

__global__ __launch_bounds__(256) void attn_kernel(
    const float* __restrict__ Wc, const float* __restrict__ bc,
    float* __restrict__ out)
{
    __shared__ __align__(16) char smem[44992];
    __half* Ah = (__half*)(smem);
    __half* Al = (__half*)(smem + 6400);
    __half* Bh = (__half*)(smem + 12800);
    __half* Bl = (__half*)(smem + 18560);
    float*  sc = (float*)(smem + 24320);
    float*  P2 = (float*)(smem);            // overlay (after scores)
    float*  vv = (float*)(smem + 12800);    // overlay (after scores)

    const int bid = blockIdx.x;
    const int tid = threadIdx.x;
    const int wid = tid >> 5, lane = tid & 31;

    const uint32_t* qg = g_q + (size_t)bid * TILE_ELEMS;
    const uint32_t* kg = g_k + (size_t)bid * TILE_ELEMS;
    const uint32_t* vg = g_v + (size_t)bid * TILE_ELEMS;

    // ---- stage q,k as fp16 hi/lo (pairs of d per thread) ----
    for (int i = tid; i < 2112; i += 256) {          // 2 * 1056 tasks
        const int isK = (i >= 1056);
        const int ii  = isK ? i - 1056 : i;
        const int s   = ii >> 4;
        const int dp  = (ii & 15) << 1;              // d pair base
        const uint2 w = *(const uint2*)((isK ? kg : qg) + s * HDIM + dp);
        const uint32_t hi01 = __byte_perm(w.x, w.y, 0x5410);
        const uint32_t lo01 = __byte_perm(w.x, w.y, 0x7632);
        __half* dh = isK ? Bh : Ah;
        __half* dl = isK ? Bl : Al;
        *(uint32_t*)(dh + s * APAD + dp) = hi01;
        *(uint32_t*)(dl + s * APAD + dp) = lo01;
    }
    __syncthreads();

    // ---- scores via HMMA: 5 m16-tiles x 9 n8-tiles ----
    const float scale = 0.17677669529663687f;        // 1/sqrt(32)
    for (int t = wid; t < 45; t += 8) {
        const int mt = t / 9, nt = t - mt * 9;
        const int r  = mt * 16 + (lane >> 2);
        const int n  = nt * 8  + (lane >> 2);
        float c[4] = {0.f, 0.f, 0.f, 0.f};
        #pragma unroll
        for (int ks = 0; ks < 2; ks++) {
            const int kk = ks * 16 + ((lane & 3) << 1);
            uint32_t a_h[4], a_l[4], b_h[2], b_l[2];
            a_h[0] = *(const uint32_t*)(Ah + r * APAD + kk);
            a_h[1] = *(const uint32_t*)(Ah + (r + 8) * APAD + kk);
            a_h[2] = *(const uint32_t*)(Ah + r * APAD + kk + 8);
            a_h[3] = *(const uint32_t*)(Ah + (r + 8) * APAD + kk + 8);
            a_l[0] = *(const uint32_t*)(Al + r * APAD + kk);
            a_l[1] = *(const uint32_t*)(Al + (r + 8) * APAD + kk);
            a_l[2] = *(const uint32_t*)(Al + r * APAD + kk + 8);
            a_l[3] = *(const uint32_t*)(Al + (r + 8) * APAD + kk + 8);
            b_h[0] = *(const uint32_t*)(Bh + n * APAD + kk);
            b_h[1] = *(const uint32_t*)(Bh + n * APAD + kk + 8);
            b_l[0] = *(const uint32_t*)(Bl + n * APAD + kk);
            b_l[1] = *(const uint32_t*)(Bl + n * APAD + kk + 8);
            hmma(c, a_h, b_h);
            hmma(c, a_h, b_l);
            hmma(c, a_l, b_h);
        }
        // store with scale + domain mask (zero) applied
        const int sq0 = mt * 16 + (lane >> 2);
        const int col = nt * 8 + ((lane & 3) << 1);
        #pragma unroll
        for (int hf = 0; hf < 2; hf++) {
            const int sq = sq0 + hf * 8;
            if (sq < 68) {
                #pragma unroll
                for (int e = 0; e < 2; e++) {
                    const int sk = col + e;
                    float v = c[hf * 2 + e] * scale;
                    const bool mz = (sq < JN && sk >= 2 * JN) ||
                                    (sq >= 2 * JN && sk < JN);
                    sc[sq * SC_STRIDE + sk] = mz ? 0.0f : v;
                }
            }
        }
    }
    __syncthreads();

    // ---- rowmax -> threshold prune -> softmax (one warp per row) ----
    {
        const float NINF = __int_as_float(0xff800000);
        for (int r = wid; r < SEQ; r += 8) {
            float* row = sc + r * SC_STRIDE;
            float e0 = row[lane];
            float e1 = row[lane + 32];
            float e2 = (lane < 2) ? row[lane + 64] : NINF;
            float mx = fmaxf(fmaxf(e0, e1), e2);
            #pragma unroll
            for (int off = 16; off > 0; off >>= 1)
                mx = fmaxf(mx, __shfl_xor_sync(0xffffffffu, mx, off));
            const float thr = mx / 9.0f;
            e0 = (fabsf(e0) <= thr) ? NEGV : e0;
            e1 = (fabsf(e1) <= thr) ? NEGV : e1;
            e2 = (fabsf(e2) <= thr) ? NEGV : e2;
            float mx2 = fmaxf(fmaxf(e0, e1), e2);
            #pragma unroll
            for (int off = 16; off > 0; off >>= 1)
                mx2 = fmaxf(mx2, __shfl_xor_sync(0xffffffffu, mx2, off));
            const float ex0 = __expf(e0 - mx2);
            const float ex1 = __expf(e1 - mx2);
            const float ex2 = (lane < 2) ? __expf(e2 - mx2) : 0.0f;
            float sum = ex0 + ex1 + ex2;
            #pragma unroll
            for (int off = 16; off > 0; off >>= 1)
                sum += __shfl_xor_sync(0xffffffffu, sum, off);
            const float inv = 1.0f / sum;
            row[lane]      = ex0 * inv;
            row[lane + 32] = ex1 * inv;
            if (lane < 2) row[lane + 64] = ex2 * inv;
        }
    }
    __syncthreads();

    // ---- stage v as fp32 (overlays Bh/Bl; k-tiles are dead now) ----
    for (int i = tid; i < 1056; i += 256) {
        const int s  = i >> 4;
        const int dp = (i & 15) << 1;
        const uint2 w = *(const uint2*)(vg + s * HDIM + dp);
        float2 f;
        f.x = __half2float(__ushort_as_half((unsigned short)(w.x & 0xffff))) +
              __half2float(__ushort_as_half((unsigned short)(w.x >> 16)));
        f.y = __half2float(__ushort_as_half((unsigned short)(w.y & 0xffff))) +
              __half2float(__ushort_as_half((unsigned short)(w.y >> 16)));
        *(float2*)(vv + s * V_STRIDE + dp) = f;
    }
    __syncthreads();

    // ---- P2 = Wc @ P : [22][66], sk in 4-wide groups (17) ----
    for (int t = tid; t < 374; t += 256) {           // 22*17
        const int j   = t / 17;
        const int skt = t - j * 17;
        float4 acc = make_float4(0.f, 0.f, 0.f, 0.f);
        const float* wrow = Wc + j * SEQ;
        for (int s = 0; s < SEQ; s++) {
            const float w = __ldg(&wrow[s]);
            const float4 p = *(const float4*)(sc + s * SC_STRIDE + skt * 4);
            acc.x += w * p.x; acc.y += w * p.y;
            acc.z += w * p.z; acc.w += w * p.w;
        }
        *(float4*)(P2 + j * P2_STRIDE + skt * 4) = acc;
    }
    __syncthreads();

    // ---- out = P2 @ v + bc : [22][32] ----
    if (tid < JN * 8) {
        const int j  = tid >> 3;
        const int d0 = (tid & 7) << 2;
        float4 acc = make_float4(0.f, 0.f, 0.f, 0.f);
        const float* prow = P2 + j * P2_STRIDE;
        for (int s = 0; s < SEQ; s++) {
            const float p = prow[s];
            const float4 v4 = *(const float4*)(vv + s * V_STRIDE + d0);
            acc.x += p * v4.x; acc.y += p * v4.y;
            acc.z += p * v4.z; acc.w += p * v4.w;
        }
        const float bcv = __ldg(&bc[j]);
        acc.x += bcv; acc.y += bcv; acc.z += bcv; acc.w += bcv;

        const int h  = bid & 7;
        const int bt = bid >> 3;
        const int b  = bt / TLEN;
        const int t  = bt - b * TLEN;
        const size_t off = ((size_t)b * (TLEN * JN) + t * JN + j) * (HEADS * HDIM)
                         + h * HDIM + d0;
        *(float4*)&out[off] = acc;
    }
}

// ---------------------------------------------------------------------------
extern "C" void kernel_launch(void* const* d_in, const int* in_sizes, int n_in,
                              void* d_out, int out_size)
{
    const float* x  = (const float*)d_in[0];
    const float* Wq = (const float*)d_in[1];
    const float* bq = (const float*)d_in[2];
    const float* Wk = (const float*)d_in[3];
    const float* bk = (const float*)d_in[4];
    const float* Wv = (const float*)d_in[5];
    const float* bv = (const float*)d_in[6];
    const float* Wc = (const float*)d_in[7];
    const float* bc = (const float*)d_in[8];
    float* out = (float*)d_out;

    wconv<<<768, 256>>>(Wq, Wk, Wv);
    qkv_gemm_tc<<<dim3(2, M_TOTAL / 128, 3), 256>>>(x, bq, bk, bv);
    attn_kernel<<<BTH, 256>>>(Wc, bc, out);
}

// round 9
// speedup vs baseline: 1.8783x; 1.0622x over previous
#include <cuda_runtime.h>
#include <cuda_fp16.h>
#include <cstdint>

// ---------------------------------------------------------------------------
// Problem constants
// ---------------------------------------------------------------------------
#define BATCH 512
#define TLEN  6
#define SEQ   66
#define INDIM 256
#define HEADS 8
#define HDIM  32
#define JN    22
#define NEGV  (-9e15f)

#define M_TOTAL (BATCH * TLEN * SEQ)          // 202752
#define BTH     (BATCH * TLEN * HEADS)        // 24576
#define TILE_ELEMS (SEQ * HDIM)               // 2112

// Scratch: q/k/v as packed fp16 hi|lo (hi = bits[0:16], lo = bits[16:32]).
__device__ uint32_t g_q[BTH * TILE_ELEMS];
__device__ uint32_t g_k[BTH * TILE_ELEMS];
__device__ uint32_t g_v[BTH * TILE_ELEMS];
__device__ __half g_wh[3 * 256 * 256];        // proj weights fp16 hi
__device__ __half g_wl[3 * 256 * 256];        // proj weights fp16 lo
__device__ __half g_wch[24 * 80];             // Wc fp16 hi, padded [24][80]
__device__ __half g_wcl[24 * 80];             // Wc fp16 lo

// ---------------------------------------------------------------------------
__device__ __forceinline__ void hmma(float* c, const uint32_t* a, const uint32_t* b) {
    asm volatile(
        "mma.sync.aligned.m16n8k16.row.col.f32.f16.f16.f32 "
        "{%0,%1,%2,%3}, {%4,%5,%6,%7}, {%8,%9}, {%0,%1,%2,%3};"
        : "+f"(c[0]), "+f"(c[1]), "+f"(c[2]), "+f"(c[3])
        : "r"(a[0]), "r"(a[1]), "r"(a[2]), "r"(a[3]), "r"(b[0]), "r"(b[1]));
}
__device__ __forceinline__ uint32_t pack2(__half a, __half b) {
    __half2 h = __halves2half2(a, b);
    return *(uint32_t*)&h;
}
__device__ __forceinline__ uint32_t pack_hilo(float v) {
    const __half h = __float2half(v);
    const __half l = __float2half(v - __half2float(h));
    return (uint32_t)__half_as_ushort(h) | ((uint32_t)__half_as_ushort(l) << 16);
}

// ---------------------------------------------------------------------------
// Kernel 0: split weights to fp16 hi/lo (block 768 handles Wc).
// ---------------------------------------------------------------------------
__global__ void wconv(const float* __restrict__ Wq, const float* __restrict__ Wk,
                      const float* __restrict__ Wv, const float* __restrict__ Wc) {
    if (blockIdx.x < 768) {
        const int i = blockIdx.x * 256 + threadIdx.x;
        const int mat = i >> 16;
        const int rem = i & 65535;
        const float* W = (mat == 0) ? Wq : (mat == 1) ? Wk : Wv;
        const float v = W[rem];
        const __half h = __float2half(v);
        g_wh[i] = h;
        g_wl[i] = __float2half(v - __half2float(h));
    } else {
        for (int i = threadIdx.x; i < 1920; i += 256) {
            const int j = i / 80, s = i - j * 80;
            const float v = (j < JN && s < SEQ) ? Wc[j * SEQ + s] : 0.0f;
            const __half h = __float2half(v);
            g_wch[i] = h;
            g_wcl[i] = __float2half(v - __half2float(h));
        }
    }
}

// ---------------------------------------------------------------------------
// Kernel 1: QKV GEMM (unchanged R5 passing version).
// ---------------------------------------------------------------------------
#define APAD 40

__global__ __launch_bounds__(256) void qkv_gemm_tc(
    const float* __restrict__ x,
    const float* __restrict__ bq, const float* __restrict__ bk,
    const float* __restrict__ bv)
{
    __shared__ __half Ash[128 * APAD];
    __shared__ __half Asl[128 * APAD];
    __shared__ __half Bsh[128 * APAD];
    __shared__ __half Bsl[128 * APAD];

    const int tid  = threadIdx.x;
    const int wid  = tid >> 5, lane = tid & 31;
    const int mat  = blockIdx.z;
    const int m0   = blockIdx.y * 128;
    const int n0g  = blockIdx.x * 128;

    const float*  xg = x + (size_t)m0 * INDIM;
    const __half* wh = g_wh + mat * 65536 + (size_t)n0g * 256;
    const __half* wl = g_wl + mat * 65536 + (size_t)n0g * 256;

    const int warpM = (wid & 1) * 64;
    const int warpN = (wid >> 1) * 32;

    float acc[4][4][4];
    #pragma unroll
    for (int i = 0; i < 4; i++)
        #pragma unroll
        for (int j = 0; j < 4; j++)
            #pragma unroll
            for (int e = 0; e < 4; e++) acc[i][j][e] = 0.0f;

    float4 pa[4];
    uint4  pbh[2], pbl[2];

    auto loadA = [&](int kc) {
        #pragma unroll
        for (int i = 0; i < 4; i++) {
            const int idx = tid + i * 256;
            const int row = idx >> 3, c4 = (idx & 7) << 2;
            pa[i] = *(const float4*)(xg + (size_t)row * INDIM + kc + c4);
        }
    };
    auto loadB = [&](int kc) {
        #pragma unroll
        for (int i = 0; i < 2; i++) {
            const int idx = tid + i * 256;
            const int row = idx >> 2, q = idx & 3;
            pbh[i] = *(const uint4*)(wh + (size_t)row * 256 + kc + q * 8);
            pbl[i] = *(const uint4*)(wl + (size_t)row * 256 + kc + q * 8);
        }
    };
    auto storeA = [&]() {
        #pragma unroll
        for (int i = 0; i < 4; i++) {
            const int idx = tid + i * 256;
            const int row = idx >> 3, c4 = (idx & 7) << 2;
            const float v0 = pa[i].x, v1 = pa[i].y, v2 = pa[i].z, v3 = pa[i].w;
            const __half h0 = __float2half(v0), h1 = __float2half(v1);
            const __half h2 = __float2half(v2), h3 = __float2half(v3);
            const __half l0 = __float2half(v0 - __half2float(h0));
            const __half l1 = __float2half(v1 - __half2float(h1));
            const __half l2 = __float2half(v2 - __half2float(h2));
            const __half l3 = __float2half(v3 - __half2float(h3));
            uint2 ph = make_uint2(pack2(h0, h1), pack2(h2, h3));
            uint2 pl = make_uint2(pack2(l0, l1), pack2(l2, l3));
            *(uint2*)(Ash + row * APAD + c4) = ph;
            *(uint2*)(Asl + row * APAD + c4) = pl;
        }
    };
    auto storeB = [&]() {
        #pragma unroll
        for (int i = 0; i < 2; i++) {
            const int idx = tid + i * 256;
            const int row = idx >> 2, q = idx & 3;
            *(uint4*)(Bsh + row * APAD + q * 8) = pbh[i];
            *(uint4*)(Bsl + row * APAD + q * 8) = pbl[i];
        }
    };

    loadA(0); loadB(0);
    storeA(); storeB();
    __syncthreads();

    for (int c = 0; c < 8; c++) {
        if (c < 7) { loadA((c + 1) * 32); loadB((c + 1) * 32); }

        #pragma unroll
        for (int ks = 0; ks < 2; ks++) {
            const int k0 = ks * 16;
            uint32_t ah[4][4], al[4][4], bh[4][2], bl[4][2];
            #pragma unroll
            for (int mf = 0; mf < 4; mf++) {
                const int r = warpM + mf * 16 + (lane >> 2);
                const int cc = k0 + ((lane & 3) << 1);
                ah[mf][0] = *(const uint32_t*)(Ash + r * APAD + cc);
                ah[mf][1] = *(const uint32_t*)(Ash + (r + 8) * APAD + cc);
                ah[mf][2] = *(const uint32_t*)(Ash + r * APAD + cc + 8);
                ah[mf][3] = *(const uint32_t*)(Ash + (r + 8) * APAD + cc + 8);
                al[mf][0] = *(const uint32_t*)(Asl + r * APAD + cc);
                al[mf][1] = *(const uint32_t*)(Asl + (r + 8) * APAD + cc);
                al[mf][2] = *(const uint32_t*)(Asl + r * APAD + cc + 8);
                al[mf][3] = *(const uint32_t*)(Asl + (r + 8) * APAD + cc + 8);
            }
            #pragma unroll
            for (int nf = 0; nf < 4; nf++) {
                const int n = warpN + nf * 8 + (lane >> 2);
                const int kk = k0 + ((lane & 3) << 1);
                bh[nf][0] = *(const uint32_t*)(Bsh + n * APAD + kk);
                bh[nf][1] = *(const uint32_t*)(Bsh + n * APAD + kk + 8);
                bl[nf][0] = *(const uint32_t*)(Bsl + n * APAD + kk);
                bl[nf][1] = *(const uint32_t*)(Bsl + n * APAD + kk + 8);
            }
            #pragma unroll
            for (int mf = 0; mf < 4; mf++)
                #pragma unroll
                for (int nf = 0; nf < 4; nf++) {
                    hmma(acc[mf][nf], ah[mf], bh[nf]);
                    hmma(acc[mf][nf], ah[mf], bl[nf]);
                    hmma(acc[mf][nf], al[mf], bh[nf]);
                }
        }
        __syncthreads();
        if (c < 7) {
            storeA(); storeB();
            __syncthreads();
        }
    }

    const float* bias = (mat == 0) ? bq : (mat == 1) ? bk : bv;
    uint32_t* dst     = (mat == 0) ? g_q : (mat == 1) ? g_k : g_v;

    #pragma unroll
    for (int nf = 0; nf < 4; nf++) {
        const int col = n0g + warpN + nf * 8 + ((lane & 3) << 1);
        const int h = col >> 5, d = col & 31;
        const float b0 = bias[col], b1 = bias[col + 1];
        #pragma unroll
        for (int mf = 0; mf < 4; mf++) {
            #pragma unroll
            for (int hf = 0; hf < 2; hf++) {
                const int m = m0 + warpM + mf * 16 + (lane >> 2) + hf * 8;
                const int bt = m / SEQ;
                const int s  = m - bt * SEQ;
                float o0 = acc[mf][nf][hf * 2 + 0] + b0;
                float o1 = acc[mf][nf][hf * 2 + 1] + b1;
                if (mat == 2) { o0 = fmaxf(o0, 0.f); o1 = fmaxf(o1, 0.f); }
                uint2 o = make_uint2(pack_hilo(o0), pack_hilo(o1));
                *(uint2*)(dst + (((size_t)(bt * HEADS + h)) * SEQ + s) * HDIM + d) = o;
            }
        }
    }
}

// ---------------------------------------------------------------------------
// Kernel 2: attention, all matrix phases on HMMA, minimal smem traffic.
//   Dynamic smem layout (bytes):
//     AH 0      q-hi [80][40]h   | after scores: AVH [32][82]h @0, AVL @5248
//     AL 6400   q-lo
//     BH 12800  k-hi [72][40]h   | after scores: VTH [32][82]h @12800, VTL @18048
//     BL 18560  k-lo             |               OUT f32 [24][36] @12800 (last)
//     SC 24320  scores f32 [68][72]
//     PH 43904  P hi [72][84]h
//     PL 56000  P lo [72][84]h     total 68096
// ---------------------------------------------------------------------------
#define SM_AH  0
#define SM_AL  6400
#define SM_BH  12800
#define SM_BL  18560
#define SM_SC  24320
#define SM_PH  43904
#define SM_PL  56000
#define SM_TOT 68096
#define SM_VTH 12800
#define SM_VTL 18048
#define SM_AVH 0
#define SM_AVL 5248
#define SM_OUT 12800

__global__ __launch_bounds__(256) void attn_kernel(
    const float* __restrict__ Wc, const float* __restrict__ bc,
    float* __restrict__ out)
{
    extern __shared__ __align__(16) char sm[];

    const int bid = blockIdx.x;
    const int tid = threadIdx.x;
    const int wid = tid >> 5, lane = tid & 31;

    const uint32_t* qg = g_q + (size_t)bid * TILE_ELEMS;
    const uint32_t* kg = g_k + (size_t)bid * TILE_ELEMS;
    const uint32_t* vg = g_v + (size_t)bid * TILE_ELEMS;

    __half* Ah = (__half*)(sm + SM_AH);
    __half* Al = (__half*)(sm + SM_AL);
    __half* Bh = (__half*)(sm + SM_BH);
    __half* Bl = (__half*)(sm + SM_BL);
    float*  sc = (float*)(sm + SM_SC);

    // ---- Phase 1: stage q,k as fp16 hi/lo [s][d] ----
    for (int i = tid; i < 2112; i += 256) {
        const int isK = (i >= 1056);
        const int ii  = isK ? i - 1056 : i;
        const int s   = ii >> 4;
        const int dp  = (ii & 15) << 1;
        const uint2 w = *(const uint2*)((isK ? kg : qg) + s * HDIM + dp);
        const uint32_t hi01 = __byte_perm(w.x, w.y, 0x5410);
        const uint32_t lo01 = __byte_perm(w.x, w.y, 0x7632);
        __half* dh = isK ? Bh : Ah;
        __half* dl = isK ? Bl : Al;
        *(uint32_t*)(dh + s * APAD + dp) = hi01;
        *(uint32_t*)(dl + s * APAD + dp) = lo01;
    }
    __syncthreads();

    // ---- Phase 2: scores. warp w<5 owns m16 row-tile mt=w, loops 9 n-tiles ----
    const float scale = 0.17677669529663687f;
    if (wid < 5) {
        const int mt = wid;
        const int r  = mt * 16 + (lane >> 2);
        const int qk = (lane & 3) << 1;
        uint32_t ah[2][4], al[2][4];
        #pragma unroll
        for (int ks = 0; ks < 2; ks++) {
            const int kk = ks * 16 + qk;
            ah[ks][0] = *(const uint32_t*)(Ah + r * APAD + kk);
            ah[ks][1] = *(const uint32_t*)(Ah + (r + 8) * APAD + kk);
            ah[ks][2] = *(const uint32_t*)(Ah + r * APAD + kk + 8);
            ah[ks][3] = *(const uint32_t*)(Ah + (r + 8) * APAD + kk + 8);
            al[ks][0] = *(const uint32_t*)(Al + r * APAD + kk);
            al[ks][1] = *(const uint32_t*)(Al + (r + 8) * APAD + kk);
            al[ks][2] = *(const uint32_t*)(Al + r * APAD + kk + 8);
            al[ks][3] = *(const uint32_t*)(Al + (r + 8) * APAD + kk + 8);
        }
        for (int nt = 0; nt < 9; nt++) {
            const int n = nt * 8 + (lane >> 2);
            float c[4] = {0.f, 0.f, 0.f, 0.f};
            #pragma unroll
            for (int ks = 0; ks < 2; ks++) {
                const int kk = ks * 16 + qk;
                uint32_t b_h[2], b_l[2];
                b_h[0] = *(const uint32_t*)(Bh + n * APAD + kk);
                b_h[1] = *(const uint32_t*)(Bh + n * APAD + kk + 8);
                b_l[0] = *(const uint32_t*)(Bl + n * APAD + kk);
                b_l[1] = *(const uint32_t*)(Bl + n * APAD + kk + 8);
                hmma(c, ah[ks], b_h);
                hmma(c, ah[ks], b_l);
                hmma(c, al[ks], b_h);
            }
            const int sq0 = mt * 16 + (lane >> 2);
            const int col = nt * 8 + ((lane & 3) << 1);
            #pragma unroll
            for (int hf = 0; hf < 2; hf++) {
                const int sq = sq0 + hf * 8;
                if (sq < 68) {
                    #pragma unroll
                    for (int e = 0; e < 2; e++) {
                        const int sk = col + e;
                        float v = c[hf * 2 + e] * scale;
                        const bool mz = (sq < JN && sk >= 2 * JN) ||
                                        (sq >= 2 * JN && sk < JN);
                        sc[sq * 72 + sk] = mz ? 0.0f : v;
                    }
                }
            }
        }
    }
    __syncthreads();

    // ---- Phase 3: softmax -> P hi/lo; zero pads; stage v transposed ----
    {
        const float NINF = __int_as_float(0xff800000);
        for (int r = wid; r < SEQ; r += 8) {
            float* row = sc + r * 72;
            float e0 = row[lane];
            float e1 = row[lane + 32];
            float e2 = (lane < 2) ? row[lane + 64] : NINF;
            float mx = fmaxf(fmaxf(e0, e1), e2);
            #pragma unroll
            for (int off = 16; off > 0; off >>= 1)
                mx = fmaxf(mx, __shfl_xor_sync(0xffffffffu, mx, off));
            const float thr = mx / 9.0f;
            e0 = (fabsf(e0) <= thr) ? NEGV : e0;
            e1 = (fabsf(e1) <= thr) ? NEGV : e1;
            e2 = (fabsf(e2) <= thr) ? NEGV : e2;
            float mx2 = fmaxf(fmaxf(e0, e1), e2);
            #pragma unroll
            for (int off = 16; off > 0; off >>= 1)
                mx2 = fmaxf(mx2, __shfl_xor_sync(0xffffffffu, mx2, off));
            const float ex0 = __expf(e0 - mx2);
            const float ex1 = __expf(e1 - mx2);
            const float ex2 = (lane < 2) ? __expf(e2 - mx2) : 0.0f;
            float sum = ex0 + ex1 + ex2;
            #pragma unroll
            for (int off = 16; off > 0; off >>= 1)
                sum += __shfl_xor_sync(0xffffffffu, sum, off);
            const float inv = 1.0f / sum;
            __half* ph = (__half*)(sm + SM_PH) + r * 84;
            __half* pl = (__half*)(sm + SM_PL) + r * 84;
            const float p0 = ex0 * inv, p1 = ex1 * inv;
            const __half h0 = __float2half(p0), h1 = __float2half(p1);
            ph[lane]      = h0;  pl[lane]      = __float2half(p0 - __half2float(h0));
            ph[lane + 32] = h1;  pl[lane + 32] = __float2half(p1 - __half2float(h1));
            if (lane < 2) {
                const float p2 = ex2 * inv;
                const __half h2 = __float2half(p2);
                ph[lane + 64] = h2;
                pl[lane + 64] = __float2half(p2 - __half2float(h2));
            } else if (lane < 20) {
                ph[lane + 64] = __ushort_as_half(0);
                pl[lane + 64] = __ushort_as_half(0);
            }
        }
        // zero P rows 66..71
        if (wid < 6) {
            const int r2 = 66 + wid;
            __half* ph = (__half*)(sm + SM_PH) + r2 * 84;
            __half* pl = (__half*)(sm + SM_PL) + r2 * 84;
            for (int c = lane; c < 84; c += 32) {
                ph[c] = __ushort_as_half(0);
                pl[c] = __ushort_as_half(0);
            }
        }
        // stage v transposed: vt[d][s] fp16 hi/lo, stride 82
        for (int i = tid; i < 1056; i += 256) {
            const int d  = i & 31;
            const int sp = (i >> 5) << 1;
            const uint32_t w0 = vg[sp * HDIM + d];
            const uint32_t w1 = vg[(sp + 1) * HDIM + d];
            *(uint32_t*)(sm + SM_VTH + d * 164 + 2 * sp) = __byte_perm(w0, w1, 0x5410);
            *(uint32_t*)(sm + SM_VTL + d * 164 + 2 * sp) = __byte_perm(w0, w1, 0x7632);
        }
        // zero vt cols 66..81
        {
            const int d = tid >> 3, cc = 66 + ((tid & 7) << 1);
            *(uint32_t*)(sm + SM_VTH + d * 164 + 2 * cc) = 0;
            *(uint32_t*)(sm + SM_VTL + d * 164 + 2 * cc) = 0;
        }
    }
    __syncthreads();

    // ---- Phase 4: AV^T = V^T @ P^T via HMMA. warps 0-3 ----
    if (wid < 4) {
        const int mt = wid & 1;
        const int ntb = (wid >> 1) ? 5 : 0;
        const int nte = (wid >> 1) ? 9 : 5;
        const int m  = mt * 16 + (lane >> 2);
        const int qk = (lane & 3) << 1;
        uint32_t ah[5][4], al[5][4];
        #pragma unroll
        for (int ks = 0; ks < 5; ks++) {
            const int kk = ks * 16 + qk;
            ah[ks][0] = *(const uint32_t*)(sm + SM_VTH + m * 164 + 2 * kk);
            ah[ks][1] = *(const uint32_t*)(sm + SM_VTH + (m + 8) * 164 + 2 * kk);
            ah[ks][2] = *(const uint32_t*)(sm + SM_VTH + m * 164 + 2 * kk + 16);
            ah[ks][3] = *(const uint32_t*)(sm + SM_VTH + (m + 8) * 164 + 2 * kk + 16);
            al[ks][0] = *(const uint32_t*)(sm + SM_VTL + m * 164 + 2 * kk);
            al[ks][1] = *(const uint32_t*)(sm + SM_VTL + (m + 8) * 164 + 2 * kk);
            al[ks][2] = *(const uint32_t*)(sm + SM_VTL + m * 164 + 2 * kk + 16);
            al[ks][3] = *(const uint32_t*)(sm + SM_VTL + (m + 8) * 164 + 2 * kk + 16);
        }
        for (int nt = ntb; nt < nte; nt++) {
            const int n = nt * 8 + (lane >> 2);
            float c[4] = {0.f, 0.f, 0.f, 0.f};
            #pragma unroll
            for (int ks = 0; ks < 5; ks++) {
                const int kk = ks * 16 + qk;
                uint32_t b_h[2], b_l[2];
                b_h[0] = *(const uint32_t*)(sm + SM_PH + n * 168 + 2 * kk);
                b_h[1] = *(const uint32_t*)(sm + SM_PH + n * 168 + 2 * kk + 16);
                b_l[0] = *(const uint32_t*)(sm + SM_PL + n * 168 + 2 * kk);
                b_l[1] = *(const uint32_t*)(sm + SM_PL + n * 168 + 2 * kk + 16);
                hmma(c, ah[ks], b_h);
                hmma(c, ah[ks], b_l);
                hmma(c, al[ks], b_h);
            }
            const int sq = nt * 8 + ((lane & 3) << 1);
            if (sq < SEQ) {
                const __half h0 = __float2half(c[0]), h1 = __float2half(c[1]);
                const __half h2 = __float2half(c[2]), h3 = __float2half(c[3]);
                *(uint32_t*)(sm + SM_AVH + m * 164 + 2 * sq) = pack2(h0, h1);
                *(uint32_t*)(sm + SM_AVL + m * 164 + 2 * sq) =
                    pack2(__float2half(c[0] - __half2float(h0)),
                          __float2half(c[1] - __half2float(h1)));
                *(uint32_t*)(sm + SM_AVH + (m + 8) * 164 + 2 * sq) = pack2(h2, h3);
                *(uint32_t*)(sm + SM_AVL + (m + 8) * 164 + 2 * sq) =
                    pack2(__float2half(c[2] - __half2float(h2)),
                          __float2half(c[3] - __half2float(h3)));
            }
        }
    }
    // zero AV^T cols 66..81 (disjoint bytes from AV stores above)
    {
        const int d = tid >> 3, cc = 66 + ((tid & 7) << 1);
        *(uint32_t*)(sm + SM_AVH + d * 164 + 2 * cc) = 0;
        *(uint32_t*)(sm + SM_AVL + d * 164 + 2 * cc) = 0;
    }
    __syncthreads();

    // ---- Phase 5: out^T = AV^T @ Wc^T via HMMA. warps 0-5 (2 mt x 3 nt) ----
    if (wid < 6) {
        const int mt = wid & 1;
        const int nt = wid >> 1;
        const int m  = mt * 16 + (lane >> 2);
        const int n  = nt * 8 + (lane >> 2);
        const int qk = (lane & 3) << 1;
        float c[4] = {0.f, 0.f, 0.f, 0.f};
        #pragma unroll
        for (int ks = 0; ks < 5; ks++) {
            const int kk = ks * 16 + qk;
            uint32_t a_h[4], a_l[4], b_h[2], b_l[2];
            a_h[0] = *(const uint32_t*)(sm + SM_AVH + m * 164 + 2 * kk);
            a_h[1] = *(const uint32_t*)(sm + SM_AVH + (m + 8) * 164 + 2 * kk);
            a_h[2] = *(const uint32_t*)(sm + SM_AVH + m * 164 + 2 * kk + 16);
            a_h[3] = *(const uint32_t*)(sm + SM_AVH + (m + 8) * 164 + 2 * kk + 16);
            a_l[0] = *(const uint32_t*)(sm + SM_AVL + m * 164 + 2 * kk);
            a_l[1] = *(const uint32_t*)(sm + SM_AVL + (m + 8) * 164 + 2 * kk);
            a_l[2] = *(const uint32_t*)(sm + SM_AVL + m * 164 + 2 * kk + 16);
            a_l[3] = *(const uint32_t*)(sm + SM_AVL + (m + 8) * 164 + 2 * kk + 16);
            b_h[0] = __ldg((const uint32_t*)(g_wch + n * 80 + kk));
            b_h[1] = __ldg((const uint32_t*)(g_wch + n * 80 + kk + 8));
            b_l[0] = __ldg((const uint32_t*)(g_wcl + n * 80 + kk));
            b_l[1] = __ldg((const uint32_t*)(g_wcl + n * 80 + kk + 8));
            hmma(c, a_h, b_h);
            hmma(c, a_h, b_l);
            hmma(c, a_l, b_h);
        }
        // fragment (row=d, col=j) -> outbuf[j][d]
        float* ob = (float*)(sm + SM_OUT);
        const int d0 = mt * 16 + (lane >> 2);
        const int j0 = nt * 8 + ((lane & 3) << 1);
        ob[j0 * 36 + d0]           = c[0];
        ob[(j0 + 1) * 36 + d0]     = c[1];
        ob[j0 * 36 + d0 + 8]       = c[2];
        ob[(j0 + 1) * 36 + d0 + 8] = c[3];
    }
    __syncthreads();

    // ---- Phase 6: add bc, write gmem ----
    if (tid < JN * 8) {
        const int j  = tid >> 3;
        const int d0 = (tid & 7) << 2;
        float4 acc = *(const float4*)(sm + SM_OUT + (j * 36 + d0) * 4);
        const float bcv = __ldg(&bc[j]);
        acc.x += bcv; acc.y += bcv; acc.z += bcv; acc.w += bcv;

        const int h  = bid & 7;
        const int bt = bid >> 3;
        const int b  = bt / TLEN;
        const int t  = bt - b * TLEN;
        const size_t off = ((size_t)b * (TLEN * JN) + t * JN + j) * (HEADS * HDIM)
                         + h * HDIM + d0;
        *(float4*)&out[off] = acc;
    }
}

// ---------------------------------------------------------------------------
extern "C" void kernel_launch(void* const* d_in, const int* in_sizes, int n_in,
                              void* d_out, int out_size)
{
    const float* x  = (const float*)d_in[0];
    const float* Wq = (const float*)d_in[1];
    const float* bq = (const float*)d_in[2];
    const float* Wk = (const float*)d_in[3];
    const float* bk = (const float*)d_in[4];
    const float* Wv = (const float*)d_in[5];
    const float* bv = (const float*)d_in[6];
    const float* Wc = (const float*)d_in[7];
    const float* bc = (const float*)d_in[8];
    float* out = (float*)d_out;

    cudaFuncSetAttribute(attn_kernel,
                         cudaFuncAttributeMaxDynamicSharedMemorySize, SM_TOT);

    wconv<<<769, 256>>>(Wq, Wk, Wv, Wc);
    qkv_gemm_tc<<<dim3(2, M_TOTAL / 128, 3), 256>>>(x, bq, bk, bv);
    attn_kernel<<<BTH, 256, SM_TOT>>>(Wc, bc, out);
}

// round 16
// speedup vs baseline: 1.9707x; 1.0492x over previous
#include <cuda_runtime.h>
#include <cuda_fp16.h>
#include <cstdint>

// ---------------------------------------------------------------------------
// Problem constants
// ---------------------------------------------------------------------------
#define BATCH 512
#define TLEN  6
#define SEQ   66
#define INDIM 256
#define HEADS 8
#define HDIM  32
#define JN    22
#define NEGV  (-9e15f)

#define M_TOTAL (BATCH * TLEN * SEQ)          // 202752
#define BTH     (BATCH * TLEN * HEADS)        // 24576
#define TILE_ELEMS (SEQ * HDIM)               // 2112

// Scratch: q/k/v as packed fp16 hi|lo (hi = bits[0:16], lo = bits[16:32]).
__device__ uint32_t g_q[BTH * TILE_ELEMS];
__device__ uint32_t g_k[BTH * TILE_ELEMS];
__device__ uint32_t g_v[BTH * TILE_ELEMS];
__device__ __half g_wh[3 * 256 * 256];        // proj weights fp16 hi
__device__ __half g_wl[3 * 256 * 256];        // proj weights fp16 lo
__device__ __half g_wch[24 * 80];             // Wc fp16 hi, padded [24][80]
__device__ __half g_wcl[24 * 80];             // Wc fp16 lo

// ---------------------------------------------------------------------------
__device__ __forceinline__ void hmma(float* c, const uint32_t* a, const uint32_t* b) {
    asm volatile(
        "mma.sync.aligned.m16n8k16.row.col.f32.f16.f16.f32 "
        "{%0,%1,%2,%3}, {%4,%5,%6,%7}, {%8,%9}, {%0,%1,%2,%3};"
        : "+f"(c[0]), "+f"(c[1]), "+f"(c[2]), "+f"(c[3])
        : "r"(a[0]), "r"(a[1]), "r"(a[2]), "r"(a[3]), "r"(b[0]), "r"(b[1]));
}
__device__ __forceinline__ uint32_t pack2(__half a, __half b) {
    __half2 h = __halves2half2(a, b);
    return *(uint32_t*)&h;
}
__device__ __forceinline__ uint32_t pack_hilo(float v) {
    const __half h = __float2half(v);
    const __half l = __float2half(v - __half2float(h));
    return (uint32_t)__half_as_ushort(h) | ((uint32_t)__half_as_ushort(l) << 16);
}

// ---------------------------------------------------------------------------
// Kernel 0: split weights to fp16 hi/lo (block 768 handles Wc).
// ---------------------------------------------------------------------------
__global__ void wconv(const float* __restrict__ Wq, const float* __restrict__ Wk,
                      const float* __restrict__ Wv, const float* __restrict__ Wc) {
    if (blockIdx.x < 768) {
        const int i = blockIdx.x * 256 + threadIdx.x;
        const int mat = i >> 16;
        const int rem = i & 65535;
        const float* W = (mat == 0) ? Wq : (mat == 1) ? Wk : Wv;
        const float v = W[rem];
        const __half h = __float2half(v);
        g_wh[i] = h;
        g_wl[i] = __float2half(v - __half2float(h));
    } else {
        for (int i = threadIdx.x; i < 1920; i += 256) {
            const int j = i / 80, s = i - j * 80;
            const float v = (j < JN && s < SEQ) ? Wc[j * SEQ + s] : 0.0f;
            const __half h = __float2half(v);
            g_wch[i] = h;
            g_wcl[i] = __float2half(v - __half2float(h));
        }
    }
}

// ---------------------------------------------------------------------------
// Kernel 1: QKV GEMM (unchanged passing version).
// ---------------------------------------------------------------------------
#define APAD 40

__global__ __launch_bounds__(256) void qkv_gemm_tc(
    const float* __restrict__ x,
    const float* __restrict__ bq, const float* __restrict__ bk,
    const float* __restrict__ bv)
{
    __shared__ __half Ash[128 * APAD];
    __shared__ __half Asl[128 * APAD];
    __shared__ __half Bsh[128 * APAD];
    __shared__ __half Bsl[128 * APAD];

    const int tid  = threadIdx.x;
    const int wid  = tid >> 5, lane = tid & 31;
    const int mat  = blockIdx.z;
    const int m0   = blockIdx.y * 128;
    const int n0g  = blockIdx.x * 128;

    const float*  xg = x + (size_t)m0 * INDIM;
    const __half* wh = g_wh + mat * 65536 + (size_t)n0g * 256;
    const __half* wl = g_wl + mat * 65536 + (size_t)n0g * 256;

    const int warpM = (wid & 1) * 64;
    const int warpN = (wid >> 1) * 32;

    float acc[4][4][4];
    #pragma unroll
    for (int i = 0; i < 4; i++)
        #pragma unroll
        for (int j = 0; j < 4; j++)
            #pragma unroll
            for (int e = 0; e < 4; e++) acc[i][j][e] = 0.0f;

    float4 pa[4];
    uint4  pbh[2], pbl[2];

    auto loadA = [&](int kc) {
        #pragma unroll
        for (int i = 0; i < 4; i++) {
            const int idx = tid + i * 256;
            const int row = idx >> 3, c4 = (idx & 7) << 2;
            pa[i] = *(const float4*)(xg + (size_t)row * INDIM + kc + c4);
        }
    };
    auto loadB = [&](int kc) {
        #pragma unroll
        for (int i = 0; i < 2; i++) {
            const int idx = tid + i * 256;
            const int row = idx >> 2, q = idx & 3;
            pbh[i] = *(const uint4*)(wh + (size_t)row * 256 + kc + q * 8);
            pbl[i] = *(const uint4*)(wl + (size_t)row * 256 + kc + q * 8);
        }
    };
    auto storeA = [&]() {
        #pragma unroll
        for (int i = 0; i < 4; i++) {
            const int idx = tid + i * 256;
            const int row = idx >> 3, c4 = (idx & 7) << 2;
            const float v0 = pa[i].x, v1 = pa[i].y, v2 = pa[i].z, v3 = pa[i].w;
            const __half h0 = __float2half(v0), h1 = __float2half(v1);
            const __half h2 = __float2half(v2), h3 = __float2half(v3);
            const __half l0 = __float2half(v0 - __half2float(h0));
            const __half l1 = __float2half(v1 - __half2float(h1));
            const __half l2 = __float2half(v2 - __half2float(h2));
            const __half l3 = __float2half(v3 - __half2float(h3));
            uint2 ph = make_uint2(pack2(h0, h1), pack2(h2, h3));
            uint2 pl = make_uint2(pack2(l0, l1), pack2(l2, l3));
            *(uint2*)(Ash + row * APAD + c4) = ph;
            *(uint2*)(Asl + row * APAD + c4) = pl;
        }
    };
    auto storeB = [&]() {
        #pragma unroll
        for (int i = 0; i < 2; i++) {
            const int idx = tid + i * 256;
            const int row = idx >> 2, q = idx & 3;
            *(uint4*)(Bsh + row * APAD + q * 8) = pbh[i];
            *(uint4*)(Bsl + row * APAD + q * 8) = pbl[i];
        }
    };

    loadA(0); loadB(0);
    storeA(); storeB();
    __syncthreads();

    for (int c = 0; c < 8; c++) {
        if (c < 7) { loadA((c + 1) * 32); loadB((c + 1) * 32); }

        #pragma unroll
        for (int ks = 0; ks < 2; ks++) {
            const int k0 = ks * 16;
            uint32_t ah[4][4], al[4][4], bh[4][2], bl[4][2];
            #pragma unroll
            for (int mf = 0; mf < 4; mf++) {
                const int r = warpM + mf * 16 + (lane >> 2);
                const int cc = k0 + ((lane & 3) << 1);
                ah[mf][0] = *(const uint32_t*)(Ash + r * APAD + cc);
                ah[mf][1] = *(const uint32_t*)(Ash + (r + 8) * APAD + cc);
                ah[mf][2] = *(const uint32_t*)(Ash + r * APAD + cc + 8);
                ah[mf][3] = *(const uint32_t*)(Ash + (r + 8) * APAD + cc + 8);
                al[mf][0] = *(const uint32_t*)(Asl + r * APAD + cc);
                al[mf][1] = *(const uint32_t*)(Asl + (r + 8) * APAD + cc);
                al[mf][2] = *(const uint32_t*)(Asl + r * APAD + cc + 8);
                al[mf][3] = *(const uint32_t*)(Asl + (r + 8) * APAD + cc + 8);
            }
            #pragma unroll
            for (int nf = 0; nf < 4; nf++) {
                const int n = warpN + nf * 8 + (lane >> 2);
                const int kk = k0 + ((lane & 3) << 1);
                bh[nf][0] = *(const uint32_t*)(Bsh + n * APAD + kk);
                bh[nf][1] = *(const uint32_t*)(Bsh + n * APAD + kk + 8);
                bl[nf][0] = *(const uint32_t*)(Bsl + n * APAD + kk);
                bl[nf][1] = *(const uint32_t*)(Bsl + n * APAD + kk + 8);
            }
            #pragma unroll
            for (int mf = 0; mf < 4; mf++)
                #pragma unroll
                for (int nf = 0; nf < 4; nf++) {
                    hmma(acc[mf][nf], ah[mf], bh[nf]);
                    hmma(acc[mf][nf], ah[mf], bl[nf]);
                    hmma(acc[mf][nf], al[mf], bh[nf]);
                }
        }
        __syncthreads();
        if (c < 7) {
            storeA(); storeB();
            __syncthreads();
        }
    }

    const float* bias = (mat == 0) ? bq : (mat == 1) ? bk : bv;
    uint32_t* dst     = (mat == 0) ? g_q : (mat == 1) ? g_k : g_v;

    #pragma unroll
    for (int nf = 0; nf < 4; nf++) {
        const int col = n0g + warpN + nf * 8 + ((lane & 3) << 1);
        const int h = col >> 5, d = col & 31;
        const float b0 = bias[col], b1 = bias[col + 1];
        #pragma unroll
        for (int mf = 0; mf < 4; mf++) {
            #pragma unroll
            for (int hf = 0; hf < 2; hf++) {
                const int m = m0 + warpM + mf * 16 + (lane >> 2) + hf * 8;
                const int bt = m / SEQ;
                const int s  = m - bt * SEQ;
                float o0 = acc[mf][nf][hf * 2 + 0] + b0;
                float o1 = acc[mf][nf][hf * 2 + 1] + b1;
                if (mat == 2) { o0 = fmaxf(o0, 0.f); o1 = fmaxf(o1, 0.f); }
                uint2 o = make_uint2(pack_hilo(o0), pack_hilo(o1));
                *(uint2*)(dst + (((size_t)(bt * HEADS + h)) * SEQ + s) * HDIM + d) = o;
            }
        }
    }
}

// ---------------------------------------------------------------------------
// Kernel 2: attention. Short critical path: grouped softmax (8-lane groups,
// group-local shfl masks), full-warp AV phase, output fused into final HMMA.
//   smem layout (bytes):
//     AH 0      q-hi [80][40]h   | after P2: AVH [32][82]h @0, AVL @5248
//     AL 6400   q-lo
//     BH 12800  k-hi [72][40]h   | after P2: VTH [32][82]h @12800, VTL @18048
//     BL 18560  k-lo
//     SC 24320  scores f32 [68][72]
//     PH 43904  P hi [72][84]h
//     PL 56000  P lo [72][84]h     total 68096
// ---------------------------------------------------------------------------
#define SM_AH  0
#define SM_AL  6400
#define SM_BH  12800
#define SM_BL  18560
#define SM_SC  24320
#define SM_PH  43904
#define SM_PL  56000
#define SM_TOT 68096
#define SM_VTH 12800
#define SM_VTL 18048
#define SM_AVH 0
#define SM_AVL 5248

__global__ __launch_bounds__(256) void attn_kernel(
    const float* __restrict__ bc, float* __restrict__ out)
{
    extern __shared__ __align__(16) char sm[];

    const int bid = blockIdx.x;
    const int tid = threadIdx.x;
    const int wid = tid >> 5, lane = tid & 31;

    const uint32_t* qg = g_q + (size_t)bid * TILE_ELEMS;
    const uint32_t* kg = g_k + (size_t)bid * TILE_ELEMS;
    const uint32_t* vg = g_v + (size_t)bid * TILE_ELEMS;

    __half* Ah = (__half*)(sm + SM_AH);
    __half* Al = (__half*)(sm + SM_AL);
    __half* Bh = (__half*)(sm + SM_BH);
    __half* Bl = (__half*)(sm + SM_BL);
    float*  sc = (float*)(sm + SM_SC);

    // ---- P1: stage q,k as fp16 hi/lo [s][d] ----
    for (int i = tid; i < 2112; i += 256) {
        const int isK = (i >= 1056);
        const int ii  = isK ? i - 1056 : i;
        const int s   = ii >> 4;
        const int dp  = (ii & 15) << 1;
        const uint2 w = *(const uint2*)((isK ? kg : qg) + s * HDIM + dp);
        const uint32_t hi01 = __byte_perm(w.x, w.y, 0x5410);
        const uint32_t lo01 = __byte_perm(w.x, w.y, 0x7632);
        __half* dh = isK ? Bh : Ah;
        __half* dl = isK ? Bl : Al;
        *(uint32_t*)(dh + s * APAD + dp) = hi01;
        *(uint32_t*)(dl + s * APAD + dp) = lo01;
    }
    __syncthreads();

    // ---- P2: scores. warp w<5 owns m16 row-tile, loops 9 n-tiles ----
    const float scale = 0.17677669529663687f;
    if (wid < 5) {
        const int mt = wid;
        const int r  = mt * 16 + (lane >> 2);
        const int qk = (lane & 3) << 1;
        uint32_t ahf[2][4], alf[2][4];
        #pragma unroll
        for (int ks = 0; ks < 2; ks++) {
            const int kk = ks * 16 + qk;
            ahf[ks][0] = *(const uint32_t*)(Ah + r * APAD + kk);
            ahf[ks][1] = *(const uint32_t*)(Ah + (r + 8) * APAD + kk);
            ahf[ks][2] = *(const uint32_t*)(Ah + r * APAD + kk + 8);
            ahf[ks][3] = *(const uint32_t*)(Ah + (r + 8) * APAD + kk + 8);
            alf[ks][0] = *(const uint32_t*)(Al + r * APAD + kk);
            alf[ks][1] = *(const uint32_t*)(Al + (r + 8) * APAD + kk);
            alf[ks][2] = *(const uint32_t*)(Al + r * APAD + kk + 8);
            alf[ks][3] = *(const uint32_t*)(Al + (r + 8) * APAD + kk + 8);
        }
        for (int nt = 0; nt < 9; nt++) {
            const int n = nt * 8 + (lane >> 2);
            float c[4] = {0.f, 0.f, 0.f, 0.f};
            #pragma unroll
            for (int ks = 0; ks < 2; ks++) {
                const int kk = ks * 16 + qk;
                uint32_t b_h[2], b_l[2];
                b_h[0] = *(const uint32_t*)(Bh + n * APAD + kk);
                b_h[1] = *(const uint32_t*)(Bh + n * APAD + kk + 8);
                b_l[0] = *(const uint32_t*)(Bl + n * APAD + kk);
                b_l[1] = *(const uint32_t*)(Bl + n * APAD + kk + 8);
                hmma(c, ahf[ks], b_h);
                hmma(c, ahf[ks], b_l);
                hmma(c, alf[ks], b_h);
            }
            const int sq0 = mt * 16 + (lane >> 2);
            const int col = nt * 8 + ((lane & 3) << 1);
            #pragma unroll
            for (int hf = 0; hf < 2; hf++) {
                const int sq = sq0 + hf * 8;
                if (sq < 68) {
                    #pragma unroll
                    for (int e = 0; e < 2; e++) {
                        const int sk = col + e;
                        float v = c[hf * 2 + e] * scale;
                        const bool mz = (sq < JN && sk >= 2 * JN) ||
                                        (sq >= 2 * JN && sk < JN);
                        sc[sq * 72 + sk] = mz ? 0.0f : v;
                    }
                }
            }
        }
    }
    __syncthreads();

    // ---- P3: grouped softmax (8-lane groups, GROUP-LOCAL shfl masks) ->
    //          P hi/lo; stage v transposed; zero all pads ----
    {
        const float NINF = __int_as_float(0xff800000);
        const int l8 = lane & 7;                         // lane within group
        const int rg = lane >> 3;                        // row-group 0..3
        const uint32_t gmask = 0xFFu << (rg * 8);        // 8-lane group mask
        #pragma unroll
        for (int it = 0; it < 3; it++) {
            const int r = it * 32 + wid * 4 + rg;        // 0..95
            if (r < 72) {
                __half* ph = (__half*)(sm + SM_PH) + r * 84;
                __half* pl = (__half*)(sm + SM_PL) + r * 84;
                if (r < SEQ) {
                    const float* row = sc + r * 72;
                    float e[9];
                    float mx = NINF;
                    #pragma unroll
                    for (int j = 0; j < 9; j++) {
                        const int cc = j * 8 + l8;
                        e[j] = (cc < SEQ) ? row[cc] : NINF;
                        mx = fmaxf(mx, e[j]);
                    }
                    mx = fmaxf(mx, __shfl_xor_sync(gmask, mx, 4));
                    mx = fmaxf(mx, __shfl_xor_sync(gmask, mx, 2));
                    mx = fmaxf(mx, __shfl_xor_sync(gmask, mx, 1));
                    const float thr = mx / 9.0f;
                    float mx2 = NINF;
                    #pragma unroll
                    for (int j = 0; j < 9; j++) {
                        e[j] = (fabsf(e[j]) <= thr) ? NEGV : e[j];
                        mx2 = fmaxf(mx2, e[j]);
                    }
                    mx2 = fmaxf(mx2, __shfl_xor_sync(gmask, mx2, 4));
                    mx2 = fmaxf(mx2, __shfl_xor_sync(gmask, mx2, 2));
                    mx2 = fmaxf(mx2, __shfl_xor_sync(gmask, mx2, 1));
                    float sum = 0.0f;
                    float ex[9];
                    #pragma unroll
                    for (int j = 0; j < 9; j++) {
                        const int cc = j * 8 + l8;
                        ex[j] = (cc < SEQ) ? __expf(e[j] - mx2) : 0.0f;
                        sum += ex[j];
                    }
                    sum += __shfl_xor_sync(gmask, sum, 4);
                    sum += __shfl_xor_sync(gmask, sum, 2);
                    sum += __shfl_xor_sync(gmask, sum, 1);
                    const float inv = 1.0f / sum;
                    #pragma unroll
                    for (int j = 0; j < 10; j++) {
                        const int cc = j * 8 + l8;
                        if (cc < 80) {
                            if (cc < SEQ) {
                                const float p = ex[j] * inv;
                                const __half h = __float2half(p);
                                ph[cc] = h;
                                pl[cc] = __float2half(p - __half2float(h));
                            } else {
                                ph[cc] = __ushort_as_half(0);
                                pl[cc] = __ushort_as_half(0);
                            }
                        }
                    }
                } else {
                    // zero pad rows 66..71 entirely (cols 0..79)
                    #pragma unroll
                    for (int j = 0; j < 10; j++) {
                        const int cc = j * 8 + l8;
                        if (cc < 80) {
                            ph[cc] = __ushort_as_half(0);
                            pl[cc] = __ushort_as_half(0);
                        }
                    }
                }
            }
        }
        // stage v transposed: vt[d][s] fp16 hi/lo, row = 164 bytes
        for (int i = tid; i < 1056; i += 256) {
            const int d  = i & 31;
            const int sp = (i >> 5) << 1;
            const uint32_t w0 = vg[sp * HDIM + d];
            const uint32_t w1 = vg[(sp + 1) * HDIM + d];
            *(uint32_t*)(sm + SM_VTH + d * 164 + 2 * sp) = __byte_perm(w0, w1, 0x5410);
            *(uint32_t*)(sm + SM_VTL + d * 164 + 2 * sp) = __byte_perm(w0, w1, 0x7632);
        }
        // zero vt cols 66..81 and AV^T pad cols 66..81
        {
            const int d = tid >> 3, cc = 66 + ((tid & 7) << 1);
            *(uint32_t*)(sm + SM_VTH + d * 164 + 2 * cc) = 0;
            *(uint32_t*)(sm + SM_VTL + d * 164 + 2 * cc) = 0;
            *(uint32_t*)(sm + SM_AVH + d * 164 + 2 * cc) = 0;
            *(uint32_t*)(sm + SM_AVL + d * 164 + 2 * cc) = 0;
        }
    }
    __syncthreads();

    // ---- P4: AV^T = V^T @ P^T via HMMA. 18 units over all 8 warps ----
    for (int u = wid; u < 18; u += 8) {
        const int mt = u / 9, nt = u - mt * 9;
        const int m  = mt * 16 + (lane >> 2);
        const int n  = nt * 8 + (lane >> 2);
        const int qk = (lane & 3) << 1;
        float c[4] = {0.f, 0.f, 0.f, 0.f};
        #pragma unroll
        for (int ks = 0; ks < 5; ks++) {
            const int kk = ks * 16 + qk;
            uint32_t a_h[4], a_l[4], b_h[2], b_l[2];
            a_h[0] = *(const uint32_t*)(sm + SM_VTH + m * 164 + 2 * kk);
            a_h[1] = *(const uint32_t*)(sm + SM_VTH + (m + 8) * 164 + 2 * kk);
            a_h[2] = *(const uint32_t*)(sm + SM_VTH + m * 164 + 2 * kk + 16);
            a_h[3] = *(const uint32_t*)(sm + SM_VTH + (m + 8) * 164 + 2 * kk + 16);
            a_l[0] = *(const uint32_t*)(sm + SM_VTL + m * 164 + 2 * kk);
            a_l[1] = *(const uint32_t*)(sm + SM_VTL + (m + 8) * 164 + 2 * kk);
            a_l[2] = *(const uint32_t*)(sm + SM_VTL + m * 164 + 2 * kk + 16);
            a_l[3] = *(const uint32_t*)(sm + SM_VTL + (m + 8) * 164 + 2 * kk + 16);
            b_h[0] = *(const uint32_t*)(sm + SM_PH + n * 168 + 2 * kk);
            b_h[1] = *(const uint32_t*)(sm + SM_PH + n * 168 + 2 * kk + 16);
            b_l[0] = *(const uint32_t*)(sm + SM_PL + n * 168 + 2 * kk);
            b_l[1] = *(const uint32_t*)(sm + SM_PL + n * 168 + 2 * kk + 16);
            hmma(c, a_h, b_h);
            hmma(c, a_h, b_l);
            hmma(c, a_l, b_h);
        }
        const int sq = nt * 8 + ((lane & 3) << 1);
        if (sq < SEQ) {
            const __half h0 = __float2half(c[0]), h1 = __float2half(c[1]);
            const __half h2 = __float2half(c[2]), h3 = __float2half(c[3]);
            *(uint32_t*)(sm + SM_AVH + m * 164 + 2 * sq) = pack2(h0, h1);
            *(uint32_t*)(sm + SM_AVL + m * 164 + 2 * sq) =
                pack2(__float2half(c[0] - __half2float(h0)),
                      __float2half(c[1] - __half2float(h1)));
            *(uint32_t*)(sm + SM_AVH + (m + 8) * 164 + 2 * sq) = pack2(h2, h3);
            *(uint32_t*)(sm + SM_AVL + (m + 8) * 164 + 2 * sq) =
                pack2(__float2half(c[2] - __half2float(h2)),
                      __float2half(c[3] - __half2float(h3)));
        }
    }
    __syncthreads();

    // ---- P5: out^T = AV^T @ Wc^T via HMMA; add bc; store straight to gmem ----
    if (wid < 6) {
        const int mt = wid & 1;
        const int nt = wid >> 1;
        const int m  = mt * 16 + (lane >> 2);
        const int n  = nt * 8 + (lane >> 2);
        const int qk = (lane & 3) << 1;
        float c[4] = {0.f, 0.f, 0.f, 0.f};
        #pragma unroll
        for (int ks = 0; ks < 5; ks++) {
            const int kk = ks * 16 + qk;
            uint32_t a_h[4], a_l[4], b_h[2], b_l[2];
            a_h[0] = *(const uint32_t*)(sm + SM_AVH + m * 164 + 2 * kk);
            a_h[1] = *(const uint32_t*)(sm + SM_AVH + (m + 8) * 164 + 2 * kk);
            a_h[2] = *(const uint32_t*)(sm + SM_AVH + m * 164 + 2 * kk + 16);
            a_h[3] = *(const uint32_t*)(sm + SM_AVH + (m + 8) * 164 + 2 * kk + 16);
            a_l[0] = *(const uint32_t*)(sm + SM_AVL + m * 164 + 2 * kk);
            a_l[1] = *(const uint32_t*)(sm + SM_AVL + (m + 8) * 164 + 2 * kk);
            a_l[2] = *(const uint32_t*)(sm + SM_AVL + m * 164 + 2 * kk + 16);
            a_l[3] = *(const uint32_t*)(sm + SM_AVL + (m + 8) * 164 + 2 * kk + 16);
            b_h[0] = __ldg((const uint32_t*)(g_wch + n * 80 + kk));
            b_h[1] = __ldg((const uint32_t*)(g_wch + n * 80 + kk + 8));
            b_l[0] = __ldg((const uint32_t*)(g_wcl + n * 80 + kk));
            b_l[1] = __ldg((const uint32_t*)(g_wcl + n * 80 + kk + 8));
            hmma(c, a_h, b_h);
            hmma(c, a_h, b_l);
            hmma(c, a_l, b_h);
        }
        // fragment (row = d, col = j) -> gmem, bias added
        const int h  = bid & 7;
        const int bt = bid >> 3;
        const int b  = bt / TLEN;
        const int t  = bt - b * TLEN;
        const size_t base = ((size_t)b * (TLEN * JN) + t * JN) * (HEADS * HDIM)
                          + h * HDIM;
        const int d0 = mt * 16 + (lane >> 2);
        const int j0 = nt * 8 + ((lane & 3) << 1);
        if (j0 < JN) {
            const float bj = __ldg(&bc[j0]);
            out[base + (size_t)j0 * 256 + d0]     = c[0] + bj;
            out[base + (size_t)j0 * 256 + d0 + 8] = c[2] + bj;
        }
        if (j0 + 1 < JN) {
            const float bj = __ldg(&bc[j0 + 1]);
            out[base + (size_t)(j0 + 1) * 256 + d0]     = c[1] + bj;
            out[base + (size_t)(j0 + 1) * 256 + d0 + 8] = c[3] + bj;
        }
    }
}

// ---------------------------------------------------------------------------
extern "C" void kernel_launch(void* const* d_in, const int* in_sizes, int n_in,
                              void* d_out, int out_size)
{
    const float* x  = (const float*)d_in[0];
    const float* Wq = (const float*)d_in[1];
    const float* bq = (const float*)d_in[2];
    const float* Wk = (const float*)d_in[3];
    const float* bk = (const float*)d_in[4];
    const float* Wv = (const float*)d_in[5];
    const float* bv = (const float*)d_in[6];
    const float* Wc = (const float*)d_in[7];
    const float* bc = (const float*)d_in[8];
    float* out = (float*)d_out;

    cudaFuncSetAttribute(attn_kernel,
                         cudaFuncAttributeMaxDynamicSharedMemorySize, SM_TOT);

    wconv<<<769, 256>>>(Wq, Wk, Wv, Wc);
    qkv_gemm_tc<<<dim3(2, M_TOTAL / 128, 3), 256>>>(x, bq, bk, bv);
    attn_kernel<<<BTH, 256, SM_TOT>>>(bc, out);
}